// round 1
// baseline (speedup 1.0000x reference)
#include <cuda_runtime.h>
#include <cuda_bf16.h>

#define BATCH  8
#define LSEQ   1024
#define DMODEL 512
#define NHEAD  8
#define DKH    64
#define DVH    512

// ---------------- scratch (static device globals; no runtime allocation) ----
__device__ float g_Q [NHEAD*BATCH*LSEQ*DKH];          // [h][b][l][dk]
__device__ float g_K [NHEAD*BATCH*LSEQ*DKH];          // [h][b][l][dk]
__device__ float g_Vt[NHEAD*BATCH*DVH*LSEQ];          // [h][b][dv][l]  (transposed)
__device__ float g_S [67108864];                      // [h][b][q][k]  (attn scores -> probs)
__device__ float g_O [NHEAD*BATCH*LSEQ*DVH];          // [h][b][l][dv]
__device__ float g_G [NHEAD*BATCH*LSEQ*DVH];          // gate logits, same layout
__device__ float g_Y [BATCH*LSEQ*DVH];                // combined heads
__device__ int   g_len[BATCH];

// ---------------- mask prep: detect bool(1B) vs int/float(4B), get lengths --
__global__ void prep_mask(const unsigned char* __restrict__ mask8) {
    __shared__ int s_violate;
    __shared__ int s_len[BATCH];
    const int t = threadIdx.x;
    if (t == 0) s_violate = 0;
    if (t < BATCH) s_len[t] = LSEQ;
    __syncthreads();
    // Bool encoding: each 1024-byte row is monotone 0...0,1...1.
    // 4-byte encodings (01 00 00 00 / 00 00 80 3f) contain a nonzero byte
    // followed by a zero byte within a row -> violation.
    for (int i = t; i < BATCH*LSEQ - 1; i += blockDim.x) {
        if ((i & (LSEQ-1)) != LSEQ-1) {
            if (mask8[i] != 0 && mask8[i+1] == 0) atomicOr(&s_violate, 1);
        }
    }
    __syncthreads();
    const bool is4 = (s_violate != 0);
    if (!is4) {
        for (int i = t; i < BATCH*LSEQ; i += blockDim.x)
            if (mask8[i] != 0) atomicMin(&s_len[i >> 10], i & (LSEQ-1));
    } else {
        const unsigned int* m32 = reinterpret_cast<const unsigned int*>(mask8);
        for (int i = t; i < BATCH*LSEQ; i += blockDim.x)
            if (m32[i] != 0) atomicMin(&s_len[i >> 10], i & (LSEQ-1));
    }
    __syncthreads();
    if (t < BATCH) g_len[t] = s_len[t];
}

// ---------------- generic batched C = A @ B^T tiled SGEMM --------------------
// A: [M,K] row-major (batch stride sA), B: [N,K] row-major (batch stride sB).
// MODE epilogues:
//  0: QK projection  -> C[((n>>6)*BATCH*LSEQ + m)*DKH + (n&63)] = acc + bias[n]
//  1: V projection   -> transposed store C[((h*BATCH+b)*DVH+d)*LSEQ+l] = acc + bias[n]
//  2: plain batched row-major store
//  3: gate GEMM      -> + bias[batch*sBias + n]
//  4: final          -> + bias[n] + resid[m*N+n], zero padded rows
#define BM 128
#define BN 128
#define BK 8
#define TM 8
#define TN 8

template<int MODE>
__global__ void __launch_bounds__(256)
gemm_abT(const float* __restrict__ A, long long sA,
         const float* __restrict__ Bm, long long sB,
         int M, int N, int K,
         float* __restrict__ C, long long sC,
         const float* __restrict__ bias, int sBias,
         const float* __restrict__ resid)
{
    __shared__ float As[BK][BM];
    __shared__ float Bs[BK][BN];

    const int tid   = threadIdx.x;
    const int batch = blockIdx.z;
    const float* Ab = A  + (long long)batch * sA;
    const float* Bb = Bm + (long long)batch * sB;

    const int bm = blockIdx.y * BM;
    const int bn = blockIdx.x * BN;

    const int loadRow = tid >> 1;         // 0..127
    const int loadCol = (tid & 1) * 4;    // 0 or 4
    const int tm = (tid >> 4) * TM;       // 0,8,...,120
    const int tn = (tid & 15) * TN;

    const float* aptr = Ab + (long long)(bm + loadRow) * K + loadCol;
    const float* bptr = Bb + (long long)(bn + loadRow) * K + loadCol;

    float acc[TM][TN];
    #pragma unroll
    for (int i = 0; i < TM; i++)
        #pragma unroll
        for (int j = 0; j < TN; j++) acc[i][j] = 0.f;

    for (int k0 = 0; k0 < K; k0 += BK) {
        float4 av = *reinterpret_cast<const float4*>(aptr + k0);
        float4 bv = *reinterpret_cast<const float4*>(bptr + k0);
        As[loadCol+0][loadRow] = av.x; As[loadCol+1][loadRow] = av.y;
        As[loadCol+2][loadRow] = av.z; As[loadCol+3][loadRow] = av.w;
        Bs[loadCol+0][loadRow] = bv.x; Bs[loadCol+1][loadRow] = bv.y;
        Bs[loadCol+2][loadRow] = bv.z; Bs[loadCol+3][loadRow] = bv.w;
        __syncthreads();
        #pragma unroll
        for (int kk = 0; kk < BK; kk++) {
            float4 a0 = *reinterpret_cast<const float4*>(&As[kk][tm]);
            float4 a1 = *reinterpret_cast<const float4*>(&As[kk][tm+4]);
            float4 b0 = *reinterpret_cast<const float4*>(&Bs[kk][tn]);
            float4 b1 = *reinterpret_cast<const float4*>(&Bs[kk][tn+4]);
            float ar[TM] = {a0.x,a0.y,a0.z,a0.w,a1.x,a1.y,a1.z,a1.w};
            float br[TN] = {b0.x,b0.y,b0.z,b0.w,b1.x,b1.y,b1.z,b1.w};
            #pragma unroll
            for (int i = 0; i < TM; i++)
                #pragma unroll
                for (int j = 0; j < TN; j++)
                    acc[i][j] = fmaf(ar[i], br[j], acc[i][j]);
        }
        __syncthreads();
    }

    #pragma unroll
    for (int i = 0; i < TM; i++) {
        const int m = bm + tm + i;
        #pragma unroll
        for (int j = 0; j < TN; j++) {
            const int n = bn + tn + j;
            float v = acc[i][j];
            if (MODE == 0) {
                v += bias[n];
                const int h = n >> 6, d = n & 63;
                C[((long long)h*(BATCH*LSEQ) + m)*DKH + d] = v;
            } else if (MODE == 1) {
                v += bias[n];
                const int h = n >> 9, d = n & 511;
                const int b = m >> 10, l = m & (LSEQ-1);
                C[(((long long)h*BATCH + b)*DVH + d)*LSEQ + l] = v;
            } else if (MODE == 2) {
                C[(long long)batch*sC + (long long)m*N + n] = v;
            } else if (MODE == 3) {
                v += bias[(long long)batch*sBias + n];
                C[(long long)batch*sC + (long long)m*N + n] = v;
            } else { // MODE == 4: final FC + bias + residual + pad-zero
                const int b = m >> 10, l = m & (LSEQ-1);
                float outv = v + bias[n] + resid[(long long)m*N + n];
                if (l >= g_len[b]) outv = 0.f;
                C[(long long)m*N + n] = outv;
            }
        }
    }
}

// ---------------- masked row softmax over S (scale 1/sqrt(64)=0.125) -------
__global__ void softmax_rows(float* __restrict__ S) {
    const int hb  = blockIdx.y;          // h*BATCH + b
    const int b   = hb & (BATCH-1);
    const int len = g_len[b];
    float* row = S + ((long long)hb * LSEQ + blockIdx.x) * LSEQ;

    __shared__ float red[256];
    const int t = threadIdx.x;

    float mx = -3.4e38f;
    for (int j = t; j < len; j += 256) mx = fmaxf(mx, row[j]);
    red[t] = mx; __syncthreads();
    for (int s = 128; s > 0; s >>= 1) {
        if (t < s) red[t] = fmaxf(red[t], red[t+s]);
        __syncthreads();
    }
    mx = red[0] * 0.125f;
    __syncthreads();

    float sum = 0.f;
    for (int j = t; j < len; j += 256) {
        float e = __expf(row[j]*0.125f - mx);
        row[j] = e;
        sum += e;
    }
    red[t] = sum; __syncthreads();
    for (int s = 128; s > 0; s >>= 1) {
        if (t < s) red[t] += red[t+s];
        __syncthreads();
    }
    const float inv = 1.f / red[0];
    for (int j = t; j < len; j += 256)      row[j] *= inv;
    for (int j = len + t; j < LSEQ; j += 256) row[j] = 0.f;
}

// ---------------- head-gate softmax + weighted combine ----------------------
__global__ void gate_combine(const float* __restrict__ G,
                             const float* __restrict__ O,
                             float* __restrict__ Y) {
    const int HS = BATCH*LSEQ*DVH;
    const int idx = blockIdx.x * blockDim.x + threadIdx.x;
    if (idx >= HS) return;
    float g[NHEAD];
    float mx = -3.4e38f;
    #pragma unroll
    for (int h = 0; h < NHEAD; h++) {
        g[h] = G[(long long)h*HS + idx];
        mx = fmaxf(mx, g[h]);
    }
    float s = 0.f;
    #pragma unroll
    for (int h = 0; h < NHEAD; h++) { g[h] = __expf(g[h] - mx); s += g[h]; }
    const float inv = 1.f / s;
    float acc = 0.f;
    #pragma unroll
    for (int h = 0; h < NHEAD; h++) acc += g[h] * O[(long long)h*HS + idx];
    Y[idx] = acc * inv;
}

// ---------------- launch ----------------------------------------------------
extern "C" void kernel_launch(void* const* d_in, const int* in_sizes, int n_in,
                              void* d_out, int out_size) {
    const float*         enc  = (const float*)d_in[0];
    const unsigned char* npm  = (const unsigned char*)d_in[1];
    // d_in[2] slf_attn_mask: redundant (key-pad mask == non_pad_mask), unused
    const float* w_q  = (const float*)d_in[3];
    const float* b_q  = (const float*)d_in[4];
    const float* w_k  = (const float*)d_in[5];
    const float* b_k  = (const float*)d_in[6];
    const float* w_v  = (const float*)d_in[7];
    const float* b_v  = (const float*)d_in[8];
    const float* w_g  = (const float*)d_in[9];
    const float* b_g  = (const float*)d_in[10];
    const float* w_fc = (const float*)d_in[11];
    const float* b_fc = (const float*)d_in[12];
    float* out = (float*)d_out;

    float *pQ,*pK,*pVt,*pS,*pO,*pG,*pY;
    cudaGetSymbolAddress((void**)&pQ,  g_Q);
    cudaGetSymbolAddress((void**)&pK,  g_K);
    cudaGetSymbolAddress((void**)&pVt, g_Vt);
    cudaGetSymbolAddress((void**)&pS,  g_S);
    cudaGetSymbolAddress((void**)&pO,  g_O);
    cudaGetSymbolAddress((void**)&pG,  g_G);
    cudaGetSymbolAddress((void**)&pY,  g_Y);

    const int M = BATCH * LSEQ;      // 8192
    dim3 blk(256);

    prep_mask<<<1, 256>>>(npm);

    // Q, K projections: [8192,512] @ [512,512]^T
    gemm_abT<0><<<dim3(DMODEL/BN, M/BM, 1), blk>>>(enc,0, w_q,0, M, NHEAD*DKH, DMODEL,
                                                   pQ,0, b_q,0, nullptr);
    gemm_abT<0><<<dim3(DMODEL/BN, M/BM, 1), blk>>>(enc,0, w_k,0, M, NHEAD*DKH, DMODEL,
                                                   pK,0, b_k,0, nullptr);
    // V projection (stored transposed): [8192,512] @ [4096,512]^T
    gemm_abT<1><<<dim3((NHEAD*DVH)/BN, M/BM, 1), blk>>>(enc,0, w_v,0, M, NHEAD*DVH, DMODEL,
                                                        pVt,0, b_v,0, nullptr);
    // S = Q @ K^T per (h,b): 64 batches of [1024,64]x[1024,64]^T
    gemm_abT<2><<<dim3(LSEQ/BN, LSEQ/BM, NHEAD*BATCH), blk>>>(
        pQ,(long long)LSEQ*DKH, pK,(long long)LSEQ*DKH,
        LSEQ, LSEQ, DKH, pS,(long long)LSEQ*LSEQ, nullptr,0, nullptr);
    // masked softmax
    softmax_rows<<<dim3(LSEQ, NHEAD*BATCH), 256>>>(pS);
    // O = P @ V: 64 batches of [1024,1024] x [512,1024]^T (V stored transposed)
    gemm_abT<2><<<dim3(DVH/BN, LSEQ/BM, NHEAD*BATCH), blk>>>(
        pS,(long long)LSEQ*LSEQ, pVt,(long long)DVH*LSEQ,
        LSEQ, DVH, LSEQ, pO,(long long)LSEQ*DVH, nullptr,0, nullptr);
    // gate logits: per-head [8192,512] @ [512,512]^T + b_gate[h]
    gemm_abT<3><<<dim3(DVH/BN, M/BM, NHEAD), blk>>>(
        pO,(long long)M*DVH, w_g,(long long)DVH*DMODEL,
        M, DVH, DMODEL, pG,(long long)M*DVH, b_g, DVH, nullptr);
    // softmax over heads + weighted sum
    gate_combine<<<(M*DVH + 255)/256, 256>>>(pG, pO, pY);
    // final FC + bias + residual + pad zeroing
    gemm_abT<4><<<dim3(DMODEL/BN, M/BM, 1), blk>>>(
        pY,0, w_fc,0, M, DMODEL, DVH, out,0, b_fc,0, enc);
}

// round 3
// speedup vs baseline: 3.3760x; 3.3760x over previous
#include <cuda_runtime.h>
#include <cuda_bf16.h>
#include <cstdint>

#define BATCH  8
#define LSEQ   1024
#define DMODEL 512
#define NHEAD  8
#define DKH    64
#define DVH    512

// ---------------- scratch (static device globals) ---------------------------
__device__ __align__(256) float g_Q [NHEAD*BATCH*LSEQ*DKH];   // [h][m][dk]
__device__ __align__(256) float g_K [NHEAD*BATCH*LSEQ*DKH];   // [h][m][dk]
__device__ __align__(256) float g_V [NHEAD*BATCH*LSEQ*DVH];   // [h][b][l][dv] natural
__device__ __align__(256) float g_S [67108864];               // [hb][q][k]
__device__ __align__(256) float g_O [NHEAD*BATCH*LSEQ*DVH];   // [h][m][dv]
__device__ __align__(256) float g_G [NHEAD*BATCH*LSEQ*DVH];
__device__ __align__(256) float g_Y [BATCH*LSEQ*DVH];
__device__ int   g_len[BATCH];

// ---------------- helpers ----------------------------------------------------
__device__ __forceinline__ uint32_t smem_u32(const void* p) {
    uint32_t a;
    asm("{ .reg .u64 t; cvta.to.shared.u64 t, %1; cvt.u32.u64 %0, t; }"
        : "=r"(a) : "l"(p));
    return a;
}
__device__ __forceinline__ void cp16(uint32_t s, const void* g) {
    asm volatile("cp.async.cg.shared.global [%0], [%1], 16;" :: "r"(s), "l"(g));
}
__device__ __forceinline__ uint32_t f2tf(float x) {
    uint32_t u;
    asm("cvt.rna.tf32.f32 %0, %1;" : "=r"(u) : "f"(x));
    return u;
}
__device__ __forceinline__ void mma_tf32(float& c0, float& c1, float& c2, float& c3,
                                         uint32_t a0, uint32_t a1, uint32_t a2, uint32_t a3,
                                         uint32_t b0, uint32_t b1) {
    asm volatile("mma.sync.aligned.m16n8k8.row.col.f32.tf32.tf32.f32 "
                 "{%0,%1,%2,%3}, {%4,%5,%6,%7}, {%8,%9}, {%0,%1,%2,%3};"
                 : "+f"(c0), "+f"(c1), "+f"(c2), "+f"(c3)
                 : "r"(a0), "r"(a1), "r"(a2), "r"(a3), "r"(b0), "r"(b1));
}

// ---------------- mask prep --------------------------------------------------
__global__ void prep_mask(const unsigned char* __restrict__ mask8) {
    __shared__ int s_violate;
    __shared__ int s_len[BATCH];
    const int t = threadIdx.x;
    if (t == 0) s_violate = 0;
    if (t < BATCH) s_len[t] = LSEQ;
    __syncthreads();
    for (int i = t; i < BATCH*LSEQ - 1; i += blockDim.x) {
        if ((i & (LSEQ-1)) != LSEQ-1) {
            if (mask8[i] != 0 && mask8[i+1] == 0) atomicOr(&s_violate, 1);
        }
    }
    __syncthreads();
    const bool is4 = (s_violate != 0);
    if (!is4) {
        for (int i = t; i < BATCH*LSEQ; i += blockDim.x)
            if (mask8[i] != 0) atomicMin(&s_len[i >> 10], i & (LSEQ-1));
    } else {
        const unsigned int* m32 = reinterpret_cast<const unsigned int*>(mask8);
        for (int i = t; i < BATCH*LSEQ; i += blockDim.x)
            if (m32[i] != 0) atomicMin(&s_len[i >> 10], i & (LSEQ-1));
    }
    __syncthreads();
    if (t < BATCH) g_len[t] = s_len[t];
}

// ---------------- tf32 mma.sync GEMM: C = A @ op(B) --------------------------
// BM=BN=128, BK=32, 256 threads (8 warps, 64x32 warp tiles).
// BKMAJOR=false: B is [N,K] row-major (weights / K-matrix)  -> C = A @ B^T
// BKMAJOR=true : B is [K,N] row-major (V matrix)            -> C = A @ B
// MODE epilogues:
//  0: QK projection  -> C[((n>>6)*8192 + m)*64 + (n&63)] = acc + bias[n]
//  1: V projection   -> C[(n>>9)*(8192*512) + m*512 + (n&511)] = acc + bias[n]
//  2: plain batched row-major store
//  3: + bias[batch*sBias + n]
//  4: + bias[n] + resid, zero padded rows
#define ASTRIDE 36            // floats per A/BT smem row (128B rows -> pad 4)
#define BNSTRIDE 136          // floats per BN smem row
#define ABYTES  (128*ASTRIDE*4)     // 18432
#define STAGEB  (2*ABYTES)          // 36864 (B region sized to max flavor)
#define SMEM_SZ (2*STAGEB)          // 73728

template<int MODE, bool BKMAJOR>
__global__ void __launch_bounds__(256, 2)
gemm_mma(const float* __restrict__ A, long long sA,
         const float* __restrict__ Bm, long long sB,
         int M, int N, int K,
         float* __restrict__ C, long long sC,
         const float* __restrict__ bias, int sBias,
         const float* __restrict__ resid)
{
    extern __shared__ char dsm[];
    const int tid  = threadIdx.x;
    const int w    = tid >> 5;
    const int lane = tid & 31;
    const int wm   = w & 1;        // 0..1
    const int wn   = w >> 1;       // 0..3
    const int batch = blockIdx.z;
    const float* Ab = A  + (long long)batch * sA;
    const float* Bb = Bm + (long long)batch * sB;
    const int bm = blockIdx.y * 128;
    const int bn = blockIdx.x * 128;

    const uint32_t smem0 = smem_u32(dsm);
    const int KC = K >> 5;

    auto load_stage = [&](int kc) {
        const int st = kc & 1;
        const uint32_t sa = smem0 + st * STAGEB;
        const uint32_t sb = sa + ABYTES;
        const int k0 = kc << 5;
        #pragma unroll
        for (int i = 0; i < 4; i++) {
            const int idx = tid + i * 256;
            const int row = idx >> 3, chk = idx & 7;
            cp16(sa + row*(ASTRIDE*4) + chk*16,
                 Ab + (long long)(bm + row) * K + k0 + chk*4);
        }
        if (!BKMAJOR) {
            #pragma unroll
            for (int i = 0; i < 4; i++) {
                const int idx = tid + i * 256;
                const int row = idx >> 3, chk = idx & 7;
                cp16(sb + row*(ASTRIDE*4) + chk*16,
                     Bb + (long long)(bn + row) * K + k0 + chk*4);
            }
        } else {
            #pragma unroll
            for (int i = 0; i < 4; i++) {
                const int idx = tid + i * 256;
                const int row = idx >> 5, chk = idx & 31;   // 32 k-rows x 32 chunks
                cp16(sb + row*(BNSTRIDE*4) + chk*16,
                     Bb + (long long)(k0 + row) * N + bn + chk*4);
            }
        }
        asm volatile("cp.async.commit_group;" ::: "memory");
    };

    float acc[4][4][4];
    #pragma unroll
    for (int i = 0; i < 4; i++)
        #pragma unroll
        for (int j = 0; j < 4; j++)
            #pragma unroll
            for (int q = 0; q < 4; q++) acc[i][j][q] = 0.f;

    load_stage(0);
    if (KC > 1) load_stage(1);

    for (int kc = 0; kc < KC; kc++) {
        if (kc + 1 < KC) asm volatile("cp.async.wait_group 1;" ::: "memory");
        else             asm volatile("cp.async.wait_group 0;" ::: "memory");
        __syncthreads();

        const int st = kc & 1;
        const float* Af = (const float*)(dsm + st * STAGEB);
        const float* Bf = (const float*)(dsm + st * STAGEB + ABYTES);

        #pragma unroll
        for (int ks = 0; ks < 4; ks++) {
            const int k0 = ks*8 + (lane & 3);
            uint32_t af[4][4];
            #pragma unroll
            for (int mt = 0; mt < 4; mt++) {
                const int r = wm*64 + mt*16 + (lane >> 2);
                af[mt][0] = f2tf(Af[r*ASTRIDE + k0]);
                af[mt][1] = f2tf(Af[(r+8)*ASTRIDE + k0]);
                af[mt][2] = f2tf(Af[r*ASTRIDE + k0 + 4]);
                af[mt][3] = f2tf(Af[(r+8)*ASTRIDE + k0 + 4]);
            }
            uint32_t bf[4][2];
            #pragma unroll
            for (int nt = 0; nt < 4; nt++) {
                const int n = wn*32 + nt*8 + (lane >> 2);
                if (!BKMAJOR) {
                    bf[nt][0] = f2tf(Bf[n*ASTRIDE + k0]);
                    bf[nt][1] = f2tf(Bf[n*ASTRIDE + k0 + 4]);
                } else {
                    bf[nt][0] = f2tf(Bf[k0*BNSTRIDE + n]);
                    bf[nt][1] = f2tf(Bf[(k0+4)*BNSTRIDE + n]);
                }
            }
            #pragma unroll
            for (int mt = 0; mt < 4; mt++)
                #pragma unroll
                for (int nt = 0; nt < 4; nt++)
                    mma_tf32(acc[mt][nt][0], acc[mt][nt][1], acc[mt][nt][2], acc[mt][nt][3],
                             af[mt][0], af[mt][1], af[mt][2], af[mt][3],
                             bf[nt][0], bf[nt][1]);
        }
        __syncthreads();
        if (kc + 2 < KC) load_stage(kc + 2);
    }

    // ---------------- epilogue ------------------------------------------------
    #pragma unroll
    for (int mt = 0; mt < 4; mt++) {
        const int r0 = bm + wm*64 + mt*16 + (lane >> 2);
        #pragma unroll
        for (int half = 0; half < 2; half++) {
            const int m = r0 + half*8;
            const int b_idx = m >> 10, l_idx = m & (LSEQ-1);
            #pragma unroll
            for (int nt = 0; nt < 4; nt++) {
                const int n = bn + wn*32 + nt*8 + (lane & 3)*2;
                float v0 = acc[mt][nt][half*2 + 0];
                float v1 = acc[mt][nt][half*2 + 1];
                if (MODE == 0) {
                    const float2 bv = *reinterpret_cast<const float2*>(&bias[n]);
                    v0 += bv.x; v1 += bv.y;
                    const int h = n >> 6, d = n & 63;
                    float2 o = {v0, v1};
                    *reinterpret_cast<float2*>(&C[((long long)h*(BATCH*LSEQ) + m)*DKH + d]) = o;
                } else if (MODE == 1) {
                    const float2 bv = *reinterpret_cast<const float2*>(&bias[n]);
                    v0 += bv.x; v1 += bv.y;
                    const int h = n >> 9, d = n & 511;
                    float2 o = {v0, v1};
                    *reinterpret_cast<float2*>(
                        &C[(long long)h*(BATCH*LSEQ)*DVH + (long long)m*DVH + d]) = o;
                } else if (MODE == 2) {
                    float2 o = {v0, v1};
                    *reinterpret_cast<float2*>(
                        &C[(long long)batch*sC + (long long)m*N + n]) = o;
                } else if (MODE == 3) {
                    const float2 bv = *reinterpret_cast<const float2*>(
                        &bias[(long long)batch*sBias + n]);
                    float2 o = {v0 + bv.x, v1 + bv.y};
                    *reinterpret_cast<float2*>(
                        &C[(long long)batch*sC + (long long)m*N + n]) = o;
                } else { // MODE 4
                    float2 o;
                    if (l_idx >= g_len[b_idx]) { o.x = 0.f; o.y = 0.f; }
                    else {
                        const float2 bv = *reinterpret_cast<const float2*>(&bias[n]);
                        const float2 rv = *reinterpret_cast<const float2*>(
                            &resid[(long long)m*N + n]);
                        o.x = v0 + bv.x + rv.x;
                        o.y = v1 + bv.y + rv.y;
                    }
                    *reinterpret_cast<float2*>(&C[(long long)m*N + n]) = o;
                }
            }
        }
    }
}

// ---------------- masked row softmax (scale 0.125) ---------------------------
__global__ void softmax_rows(float* __restrict__ S) {
    const int hb  = blockIdx.y;
    const int b   = hb & (BATCH-1);
    const int len = g_len[b];
    float* row = S + ((long long)hb * LSEQ + blockIdx.x) * LSEQ;

    __shared__ float red[256];
    const int t = threadIdx.x;

    float mx = -3.4e38f;
    for (int j = t; j < len; j += 256) mx = fmaxf(mx, row[j]);
    red[t] = mx; __syncthreads();
    for (int s = 128; s > 0; s >>= 1) {
        if (t < s) red[t] = fmaxf(red[t], red[t+s]);
        __syncthreads();
    }
    mx = red[0] * 0.125f;
    __syncthreads();

    float sum = 0.f;
    for (int j = t; j < len; j += 256) {
        float e = __expf(row[j]*0.125f - mx);
        row[j] = e;
        sum += e;
    }
    red[t] = sum; __syncthreads();
    for (int s = 128; s > 0; s >>= 1) {
        if (t < s) red[t] += red[t+s];
        __syncthreads();
    }
    const float inv = 1.f / red[0];
    for (int j = t; j < len; j += 256)        row[j] *= inv;
    for (int j = len + t; j < LSEQ; j += 256) row[j] = 0.f;
}

// ---------------- head-gate softmax + weighted combine -----------------------
__global__ void gate_combine(const float* __restrict__ G,
                             const float* __restrict__ O,
                             float* __restrict__ Y) {
    const int HS = BATCH*LSEQ*DVH;
    const int idx = blockIdx.x * blockDim.x + threadIdx.x;
    if (idx >= HS) return;
    float g[NHEAD];
    float mx = -3.4e38f;
    #pragma unroll
    for (int h = 0; h < NHEAD; h++) {
        g[h] = G[(long long)h*HS + idx];
        mx = fmaxf(mx, g[h]);
    }
    float s = 0.f;
    #pragma unroll
    for (int h = 0; h < NHEAD; h++) { g[h] = __expf(g[h] - mx); s += g[h]; }
    const float inv = 1.f / s;
    float acc = 0.f;
    #pragma unroll
    for (int h = 0; h < NHEAD; h++) acc += g[h] * O[(long long)h*HS + idx];
    Y[idx] = acc * inv;
}

// ---------------- launch ------------------------------------------------------
extern "C" void kernel_launch(void* const* d_in, const int* in_sizes, int n_in,
                              void* d_out, int out_size) {
    const float*         enc  = (const float*)d_in[0];
    const unsigned char* npm  = (const unsigned char*)d_in[1];
    const float* w_q  = (const float*)d_in[3];
    const float* b_q  = (const float*)d_in[4];
    const float* w_k  = (const float*)d_in[5];
    const float* b_k  = (const float*)d_in[6];
    const float* w_v  = (const float*)d_in[7];
    const float* b_v  = (const float*)d_in[8];
    const float* w_g  = (const float*)d_in[9];
    const float* b_g  = (const float*)d_in[10];
    const float* w_fc = (const float*)d_in[11];
    const float* b_fc = (const float*)d_in[12];
    float* out = (float*)d_out;

    float *pQ,*pK,*pV,*pS,*pO,*pG,*pY;
    cudaGetSymbolAddress((void**)&pQ, g_Q);
    cudaGetSymbolAddress((void**)&pK, g_K);
    cudaGetSymbolAddress((void**)&pV, g_V);
    cudaGetSymbolAddress((void**)&pS, g_S);
    cudaGetSymbolAddress((void**)&pO, g_O);
    cudaGetSymbolAddress((void**)&pG, g_G);
    cudaGetSymbolAddress((void**)&pY, g_Y);

    cudaFuncSetAttribute(gemm_mma<0,false>, cudaFuncAttributeMaxDynamicSharedMemorySize, SMEM_SZ);
    cudaFuncSetAttribute(gemm_mma<1,false>, cudaFuncAttributeMaxDynamicSharedMemorySize, SMEM_SZ);
    cudaFuncSetAttribute(gemm_mma<2,false>, cudaFuncAttributeMaxDynamicSharedMemorySize, SMEM_SZ);
    cudaFuncSetAttribute(gemm_mma<2,true >, cudaFuncAttributeMaxDynamicSharedMemorySize, SMEM_SZ);
    cudaFuncSetAttribute(gemm_mma<3,false>, cudaFuncAttributeMaxDynamicSharedMemorySize, SMEM_SZ);
    cudaFuncSetAttribute(gemm_mma<4,false>, cudaFuncAttributeMaxDynamicSharedMemorySize, SMEM_SZ);

    const int M = BATCH * LSEQ;      // 8192
    dim3 blk(256);

    prep_mask<<<1, 256>>>(npm);

    // Q, K projections: [8192,512] @ [512,512]^T
    gemm_mma<0,false><<<dim3(DMODEL/128, M/128, 1), blk, SMEM_SZ>>>(
        enc,0, w_q,0, M, NHEAD*DKH, DMODEL, pQ,0, b_q,0, nullptr);
    gemm_mma<0,false><<<dim3(DMODEL/128, M/128, 1), blk, SMEM_SZ>>>(
        enc,0, w_k,0, M, NHEAD*DKH, DMODEL, pK,0, b_k,0, nullptr);
    // V projection (natural layout): [8192,4096]
    gemm_mma<1,false><<<dim3((NHEAD*DVH)/128, M/128, 1), blk, SMEM_SZ>>>(
        enc,0, w_v,0, M, NHEAD*DVH, DMODEL, pV,0, b_v,0, nullptr);
    // S = Q @ K^T per (h,b)
    gemm_mma<2,false><<<dim3(LSEQ/128, LSEQ/128, NHEAD*BATCH), blk, SMEM_SZ>>>(
        pQ,(long long)LSEQ*DKH, pK,(long long)LSEQ*DKH,
        LSEQ, LSEQ, DKH, pS,(long long)LSEQ*LSEQ, nullptr,0, nullptr);
    softmax_rows<<<dim3(LSEQ, NHEAD*BATCH), 256>>>(pS);
    // O = P @ V  (V is [K=l, N=dv] row-major per (h,b) -> BKMAJOR)
    gemm_mma<2,true><<<dim3(DVH/128, LSEQ/128, NHEAD*BATCH), blk, SMEM_SZ>>>(
        pS,(long long)LSEQ*LSEQ, pV,(long long)LSEQ*DVH,
        LSEQ, DVH, LSEQ, pO,(long long)LSEQ*DVH, nullptr,0, nullptr);
    // gate logits: per-head [8192,512] @ [512,512]^T + b_gate[h]
    gemm_mma<3,false><<<dim3(DVH/128, M/128, NHEAD), blk, SMEM_SZ>>>(
        pO,(long long)M*DVH, w_g,(long long)DVH*DMODEL,
        M, DVH, DMODEL, pG,(long long)M*DVH, b_g, DVH, nullptr);
    gate_combine<<<(M*DVH + 255)/256, 256>>>(pG, pO, pY);
    // final FC + bias + residual + pad zeroing
    gemm_mma<4,false><<<dim3(DMODEL/128, M/128, 1), blk, SMEM_SZ>>>(
        pY,0, w_fc,0, M, DMODEL, DVH, out,0, b_fc,0, enc);
}

// round 4
// speedup vs baseline: 5.3450x; 1.5833x over previous
#include <cuda_runtime.h>
#include <cuda_bf16.h>
#include <cstdint>

#define BATCH  8
#define LSEQ   1024
#define DMODEL 512
#define NHEAD  8
#define DKH    64
#define DVH    512

// ---------------- scratch (static device globals, zero-initialized) ---------
// Padded regions (rows/cols >= len[b]) are NEVER written and stay 0 forever;
// all consumers of padded data either skip it or discard it row-locally.
__device__ __align__(256) float g_Q [NHEAD*BATCH*LSEQ*DKH];   // [h][m][dk]
__device__ __align__(256) float g_K [NHEAD*BATCH*LSEQ*DKH];   // [h][m][dk]
__device__ __align__(256) float g_V [NHEAD*BATCH*LSEQ*DVH];   // [h][b][l][dv]
__device__ __align__(256) float g_S [67108864];               // [hb][q][k]
__device__ __align__(256) float g_O [NHEAD*BATCH*LSEQ*DVH];   // [h][m][dv]
__device__ __align__(256) float g_G [NHEAD*BATCH*LSEQ*DVH];
__device__ __align__(256) float g_Y [BATCH*LSEQ*DVH];
__device__ int   g_len[BATCH];

// ---------------- helpers ----------------------------------------------------
__device__ __forceinline__ uint32_t smem_u32(const void* p) {
    uint32_t a;
    asm("{ .reg .u64 t; cvta.to.shared.u64 t, %1; cvt.u32.u64 %0, t; }"
        : "=r"(a) : "l"(p));
    return a;
}
__device__ __forceinline__ void cp16(uint32_t s, const void* g) {
    asm volatile("cp.async.cg.shared.global [%0], [%1], 16;" :: "r"(s), "l"(g));
}
// tf32 mma fed with raw fp32 bits (HW truncates mantissa; ~2x rounding error
// vs cvt.rna, still far under the 1e-3 gate, saves all ALU cvt traffic)
__device__ __forceinline__ void mma_tf32(float& c0, float& c1, float& c2, float& c3,
                                         uint32_t a0, uint32_t a1, uint32_t a2, uint32_t a3,
                                         uint32_t b0, uint32_t b1) {
    asm volatile("mma.sync.aligned.m16n8k8.row.col.f32.tf32.tf32.f32 "
                 "{%0,%1,%2,%3}, {%4,%5,%6,%7}, {%8,%9}, {%0,%1,%2,%3};"
                 : "+f"(c0), "+f"(c1), "+f"(c2), "+f"(c3)
                 : "r"(a0), "r"(a1), "r"(a2), "r"(a3), "r"(b0), "r"(b1));
}

// ---------------- mask prep --------------------------------------------------
__global__ void prep_mask(const unsigned char* __restrict__ mask8) {
    __shared__ int s_violate;
    __shared__ int s_len[BATCH];
    const int t = threadIdx.x;
    if (t == 0) s_violate = 0;
    if (t < BATCH) s_len[t] = LSEQ;
    __syncthreads();
    for (int i = t; i < BATCH*LSEQ - 1; i += blockDim.x) {
        if ((i & (LSEQ-1)) != LSEQ-1) {
            if (mask8[i] != 0 && mask8[i+1] == 0) atomicOr(&s_violate, 1);
        }
    }
    __syncthreads();
    const bool is4 = (s_violate != 0);
    if (!is4) {
        for (int i = t; i < BATCH*LSEQ; i += blockDim.x)
            if (mask8[i] != 0) atomicMin(&s_len[i >> 10], i & (LSEQ-1));
    } else {
        const unsigned int* m32 = reinterpret_cast<const unsigned int*>(mask8);
        for (int i = t; i < BATCH*LSEQ; i += blockDim.x)
            if (m32[i] != 0) atomicMin(&s_len[i >> 10], i & (LSEQ-1));
    }
    __syncthreads();
    if (t < BATCH) g_len[t] = s_len[t];
}

// ---------------- tf32 mma.sync GEMM: C = A @ op(B) --------------------------
// BM=BN=128, BK=32, 256 threads (8 warps, 64x32 warp tiles), 3-stage pipeline.
// SKIP: 0 none; 1 skip row-tiles with (bm&1023)>=len[bm>>10];
//       2 S-mode: batch=hb, skip bm>=len || bn>=len;
//       3 PV-mode: batch=hb, skip bm>=len, clamp K-loop to ceil(len/32)*32;
//       4 final: zero-fill padded row-tiles (output must be written).
#define ASTRIDE 36
#define BNSTRIDE 136
#define ABYTES  (128*ASTRIDE*4)     // 18432
#define STAGEB  (2*ABYTES)          // 36864
#define SMEM_SZ (3*STAGEB)          // 110592

template<int MODE, bool BKMAJOR, int SKIP>
__global__ void __launch_bounds__(256, 2)
gemm_mma(const float* __restrict__ A, long long sA,
         const float* __restrict__ Bm, long long sB,
         int M, int N, int K,
         float* __restrict__ C, long long sC,
         const float* __restrict__ bias, int sBias,
         const float* __restrict__ resid)
{
    extern __shared__ char dsm[];
    const int tid  = threadIdx.x;
    const int w    = tid >> 5;
    const int lane = tid & 31;
    const int wm   = w & 1;
    const int wn   = w >> 1;
    const int batch = blockIdx.z;
    const int bm = blockIdx.y * 128;
    const int bn = blockIdx.x * 128;

    int Keff = K;
    if (SKIP == 1) {
        if ((bm & (LSEQ-1)) >= g_len[bm >> 10]) return;
    } else if (SKIP == 2) {
        const int L = g_len[batch & (BATCH-1)];
        if (bm >= L || bn >= L) return;
    } else if (SKIP == 3) {
        const int L = g_len[batch & (BATCH-1)];
        if (bm >= L) return;
        Keff = (L + 31) & ~31;
    } else if (SKIP == 4) {
        if ((bm & (LSEQ-1)) >= g_len[bm >> 10]) {
            // fully padded output tile: write zeros
            const float4 z = {0.f, 0.f, 0.f, 0.f};
            for (int i = tid; i < 128*32; i += 256) {
                const int r = i >> 5, c4 = i & 31;
                *reinterpret_cast<float4*>(&C[(long long)(bm + r)*N + bn + c4*4]) = z;
            }
            return;
        }
    }

    const float* Ab = A  + (long long)batch * sA;
    const float* Bb = Bm + (long long)batch * sB;
    const uint32_t smem0 = smem_u32(dsm);
    const int KC = Keff >> 5;

    auto load_stage = [&](int kc) {
        const int st = kc % 3;
        const uint32_t sa = smem0 + st * STAGEB;
        const uint32_t sb = sa + ABYTES;
        const int k0 = kc << 5;
        #pragma unroll
        for (int i = 0; i < 4; i++) {
            const int idx = tid + i * 256;
            const int row = idx >> 3, chk = idx & 7;
            cp16(sa + row*(ASTRIDE*4) + chk*16,
                 Ab + (long long)(bm + row) * K + k0 + chk*4);
        }
        if (!BKMAJOR) {
            #pragma unroll
            for (int i = 0; i < 4; i++) {
                const int idx = tid + i * 256;
                const int row = idx >> 3, chk = idx & 7;
                cp16(sb + row*(ASTRIDE*4) + chk*16,
                     Bb + (long long)(bn + row) * K + k0 + chk*4);
            }
        } else {
            #pragma unroll
            for (int i = 0; i < 4; i++) {
                const int idx = tid + i * 256;
                const int row = idx >> 5, chk = idx & 31;
                cp16(sb + row*(BNSTRIDE*4) + chk*16,
                     Bb + (long long)(k0 + row) * N + bn + chk*4);
            }
        }
        asm volatile("cp.async.commit_group;" ::: "memory");
    };

    float acc[4][4][4];
    #pragma unroll
    for (int i = 0; i < 4; i++)
        #pragma unroll
        for (int j = 0; j < 4; j++)
            #pragma unroll
            for (int q = 0; q < 4; q++) acc[i][j][q] = 0.f;

    load_stage(0);
    if (KC > 1) load_stage(1);

    for (int kc = 0; kc < KC; kc++) {
        if (kc + 1 < KC) asm volatile("cp.async.wait_group 1;" ::: "memory");
        else             asm volatile("cp.async.wait_group 0;" ::: "memory");
        __syncthreads();
        if (kc + 2 < KC) load_stage(kc + 2);   // writes buffer (kc-1)%3: safe after barrier

        const int st = kc % 3;
        const float* Af = (const float*)(dsm + st * STAGEB);
        const float* Bf = (const float*)(dsm + st * STAGEB + ABYTES);

        #pragma unroll
        for (int ks = 0; ks < 4; ks++) {
            const int k0 = ks*8 + (lane & 3);
            uint32_t af[4][4];
            #pragma unroll
            for (int mt = 0; mt < 4; mt++) {
                const int r = wm*64 + mt*16 + (lane >> 2);
                af[mt][0] = __float_as_uint(Af[r*ASTRIDE + k0]);
                af[mt][1] = __float_as_uint(Af[(r+8)*ASTRIDE + k0]);
                af[mt][2] = __float_as_uint(Af[r*ASTRIDE + k0 + 4]);
                af[mt][3] = __float_as_uint(Af[(r+8)*ASTRIDE + k0 + 4]);
            }
            uint32_t bf[4][2];
            #pragma unroll
            for (int nt = 0; nt < 4; nt++) {
                const int n = wn*32 + nt*8 + (lane >> 2);
                if (!BKMAJOR) {
                    bf[nt][0] = __float_as_uint(Bf[n*ASTRIDE + k0]);
                    bf[nt][1] = __float_as_uint(Bf[n*ASTRIDE + k0 + 4]);
                } else {
                    bf[nt][0] = __float_as_uint(Bf[k0*BNSTRIDE + n]);
                    bf[nt][1] = __float_as_uint(Bf[(k0+4)*BNSTRIDE + n]);
                }
            }
            #pragma unroll
            for (int mt = 0; mt < 4; mt++)
                #pragma unroll
                for (int nt = 0; nt < 4; nt++)
                    mma_tf32(acc[mt][nt][0], acc[mt][nt][1], acc[mt][nt][2], acc[mt][nt][3],
                             af[mt][0], af[mt][1], af[mt][2], af[mt][3],
                             bf[nt][0], bf[nt][1]);
        }
    }

    // ---------------- epilogue ------------------------------------------------
    #pragma unroll
    for (int mt = 0; mt < 4; mt++) {
        const int r0 = bm + wm*64 + mt*16 + (lane >> 2);
        #pragma unroll
        for (int half = 0; half < 2; half++) {
            const int m = r0 + half*8;
            const int b_idx = m >> 10, l_idx = m & (LSEQ-1);
            #pragma unroll
            for (int nt = 0; nt < 4; nt++) {
                const int n = bn + wn*32 + nt*8 + (lane & 3)*2;
                float v0 = acc[mt][nt][half*2 + 0];
                float v1 = acc[mt][nt][half*2 + 1];
                if (MODE == 0) {
                    const float2 bv = *reinterpret_cast<const float2*>(&bias[n]);
                    v0 += bv.x; v1 += bv.y;
                    const int h = n >> 6, d = n & 63;
                    float2 o = {v0, v1};
                    *reinterpret_cast<float2*>(&C[((long long)h*(BATCH*LSEQ) + m)*DKH + d]) = o;
                } else if (MODE == 1) {
                    const float2 bv = *reinterpret_cast<const float2*>(&bias[n]);
                    v0 += bv.x; v1 += bv.y;
                    const int h = n >> 9, d = n & 511;
                    float2 o = {v0, v1};
                    *reinterpret_cast<float2*>(
                        &C[(long long)h*(BATCH*LSEQ)*DVH + (long long)m*DVH + d]) = o;
                } else if (MODE == 2) {
                    float2 o = {v0, v1};
                    *reinterpret_cast<float2*>(
                        &C[(long long)batch*sC + (long long)m*N + n]) = o;
                } else if (MODE == 3) {
                    const float2 bv = *reinterpret_cast<const float2*>(
                        &bias[(long long)batch*sBias + n]);
                    float2 o = {v0 + bv.x, v1 + bv.y};
                    *reinterpret_cast<float2*>(
                        &C[(long long)batch*sC + (long long)m*N + n]) = o;
                } else { // MODE 4
                    float2 o;
                    if (l_idx >= g_len[b_idx]) { o.x = 0.f; o.y = 0.f; }
                    else {
                        const float2 bv = *reinterpret_cast<const float2*>(&bias[n]);
                        const float2 rv = *reinterpret_cast<const float2*>(
                            &resid[(long long)m*N + n]);
                        o.x = v0 + bv.x + rv.x;
                        o.y = v1 + bv.y + rv.y;
                    }
                    *reinterpret_cast<float2*>(&C[(long long)m*N + n]) = o;
                }
            }
        }
    }
}

// ---------------- masked row softmax, single pass, row in registers ----------
__global__ void softmax_rows(float* __restrict__ S) {
    const int hb  = blockIdx.y;
    const int len = g_len[hb & (BATCH-1)];
    const int q   = blockIdx.x;
    if (q >= len) return;                    // padded rows: S stays 0, never used
    float4* row = reinterpret_cast<float4*>(S + ((long long)hb * LSEQ + q) * LSEQ);

    const int t = threadIdx.x;
    const float4 v = row[t];
    const int j0 = t * 4;
    const float NEG = -1e30f;
    float x0 = (j0+0 < len) ? v.x : NEG;
    float x1 = (j0+1 < len) ? v.y : NEG;
    float x2 = (j0+2 < len) ? v.z : NEG;
    float x3 = (j0+3 < len) ? v.w : NEG;

    __shared__ float rmax[8], rsum[8];
    float mx = fmaxf(fmaxf(x0, x1), fmaxf(x2, x3));
    #pragma unroll
    for (int o = 16; o; o >>= 1) mx = fmaxf(mx, __shfl_xor_sync(~0u, mx, o));
    if ((t & 31) == 0) rmax[t >> 5] = mx;
    __syncthreads();
    mx = rmax[0];
    #pragma unroll
    for (int i = 1; i < 8; i++) mx = fmaxf(mx, rmax[i]);
    mx *= 0.125f;

    const float e0 = __expf(x0*0.125f - mx);
    const float e1 = __expf(x1*0.125f - mx);
    const float e2 = __expf(x2*0.125f - mx);
    const float e3 = __expf(x3*0.125f - mx);
    float s = e0 + e1 + e2 + e3;
    #pragma unroll
    for (int o = 16; o; o >>= 1) s += __shfl_xor_sync(~0u, s, o);
    if ((t & 31) == 0) rsum[t >> 5] = s;
    __syncthreads();
    s = rsum[0];
    #pragma unroll
    for (int i = 1; i < 8; i++) s += rsum[i];
    const float inv = 1.f / s;

    float4 o = {e0*inv, e1*inv, e2*inv, e3*inv};
    row[t] = o;
}

// ---------------- head-gate softmax + weighted combine (float4) --------------
__global__ void gate_combine(const float* __restrict__ G,
                             const float* __restrict__ O,
                             float* __restrict__ Y) {
    const int HS4 = BATCH*LSEQ*DVH/4;
    const int i = blockIdx.x * blockDim.x + threadIdx.x;
    if (i >= HS4) return;
    const int m = i >> 7;                 // (i*4)/512
    if ((m & (LSEQ-1)) >= g_len[m >> 10]) return;   // padded: Y stays 0, discarded

    const float4* G4 = reinterpret_cast<const float4*>(G);
    const float4* O4 = reinterpret_cast<const float4*>(O);
    float4 g[NHEAD];
    #pragma unroll
    for (int h = 0; h < NHEAD; h++) g[h] = G4[(long long)h*HS4 + i];
    float4 mx = g[0];
    #pragma unroll
    for (int h = 1; h < NHEAD; h++) {
        mx.x = fmaxf(mx.x, g[h].x); mx.y = fmaxf(mx.y, g[h].y);
        mx.z = fmaxf(mx.z, g[h].z); mx.w = fmaxf(mx.w, g[h].w);
    }
    float4 acc = {0,0,0,0}, ssum = {0,0,0,0};
    #pragma unroll
    for (int h = 0; h < NHEAD; h++) {
        const float4 o = O4[(long long)h*HS4 + i];
        const float ex = __expf(g[h].x - mx.x), ey = __expf(g[h].y - mx.y);
        const float ez = __expf(g[h].z - mx.z), ew = __expf(g[h].w - mx.w);
        ssum.x += ex; ssum.y += ey; ssum.z += ez; ssum.w += ew;
        acc.x += ex*o.x; acc.y += ey*o.y; acc.z += ez*o.z; acc.w += ew*o.w;
    }
    float4 y = {acc.x/ssum.x, acc.y/ssum.y, acc.z/ssum.z, acc.w/ssum.w};
    reinterpret_cast<float4*>(Y)[i] = y;
}

// ---------------- launch ------------------------------------------------------
extern "C" void kernel_launch(void* const* d_in, const int* in_sizes, int n_in,
                              void* d_out, int out_size) {
    const float*         enc  = (const float*)d_in[0];
    const unsigned char* npm  = (const unsigned char*)d_in[1];
    const float* w_q  = (const float*)d_in[3];
    const float* b_q  = (const float*)d_in[4];
    const float* w_k  = (const float*)d_in[5];
    const float* b_k  = (const float*)d_in[6];
    const float* w_v  = (const float*)d_in[7];
    const float* b_v  = (const float*)d_in[8];
    const float* w_g  = (const float*)d_in[9];
    const float* b_g  = (const float*)d_in[10];
    const float* w_fc = (const float*)d_in[11];
    const float* b_fc = (const float*)d_in[12];
    float* out = (float*)d_out;

    float *pQ,*pK,*pV,*pS,*pO,*pG,*pY;
    cudaGetSymbolAddress((void**)&pQ, g_Q);
    cudaGetSymbolAddress((void**)&pK, g_K);
    cudaGetSymbolAddress((void**)&pV, g_V);
    cudaGetSymbolAddress((void**)&pS, g_S);
    cudaGetSymbolAddress((void**)&pO, g_O);
    cudaGetSymbolAddress((void**)&pG, g_G);
    cudaGetSymbolAddress((void**)&pY, g_Y);

    cudaFuncSetAttribute(gemm_mma<0,false,1>, cudaFuncAttributeMaxDynamicSharedMemorySize, SMEM_SZ);
    cudaFuncSetAttribute(gemm_mma<1,false,1>, cudaFuncAttributeMaxDynamicSharedMemorySize, SMEM_SZ);
    cudaFuncSetAttribute(gemm_mma<2,false,2>, cudaFuncAttributeMaxDynamicSharedMemorySize, SMEM_SZ);
    cudaFuncSetAttribute(gemm_mma<2,true ,3>, cudaFuncAttributeMaxDynamicSharedMemorySize, SMEM_SZ);
    cudaFuncSetAttribute(gemm_mma<3,false,1>, cudaFuncAttributeMaxDynamicSharedMemorySize, SMEM_SZ);
    cudaFuncSetAttribute(gemm_mma<4,false,4>, cudaFuncAttributeMaxDynamicSharedMemorySize, SMEM_SZ);

    const int M = BATCH * LSEQ;      // 8192
    dim3 blk(256);

    prep_mask<<<1, 256>>>(npm);

    // Q, K projections: [8192,512] @ [512,512]^T
    gemm_mma<0,false,1><<<dim3(DMODEL/128, M/128, 1), blk, SMEM_SZ>>>(
        enc,0, w_q,0, M, NHEAD*DKH, DMODEL, pQ,0, b_q,0, nullptr);
    gemm_mma<0,false,1><<<dim3(DMODEL/128, M/128, 1), blk, SMEM_SZ>>>(
        enc,0, w_k,0, M, NHEAD*DKH, DMODEL, pK,0, b_k,0, nullptr);
    // V projection (natural layout): [8192,4096]
    gemm_mma<1,false,1><<<dim3((NHEAD*DVH)/128, M/128, 1), blk, SMEM_SZ>>>(
        enc,0, w_v,0, M, NHEAD*DVH, DMODEL, pV,0, b_v,0, nullptr);
    // S = Q @ K^T per (h,b), skipping masked row/col tiles
    gemm_mma<2,false,2><<<dim3(LSEQ/128, LSEQ/128, NHEAD*BATCH), blk, SMEM_SZ>>>(
        pQ,(long long)LSEQ*DKH, pK,(long long)LSEQ*DKH,
        LSEQ, LSEQ, DKH, pS,(long long)LSEQ*LSEQ, nullptr,0, nullptr);
    softmax_rows<<<dim3(LSEQ, NHEAD*BATCH), 256>>>(pS);
    // O = P @ V (V is [K=l, N=dv] per (h,b)), K-loop clamped to len
    gemm_mma<2,true,3><<<dim3(DVH/128, LSEQ/128, NHEAD*BATCH), blk, SMEM_SZ>>>(
        pS,(long long)LSEQ*LSEQ, pV,(long long)LSEQ*DVH,
        LSEQ, DVH, LSEQ, pO,(long long)LSEQ*DVH, nullptr,0, nullptr);
    // gate logits: per-head [8192,512] @ [512,512]^T + b_gate[h]
    gemm_mma<3,false,1><<<dim3(DVH/128, M/128, NHEAD), blk, SMEM_SZ>>>(
        pO,(long long)M*DVH, w_g,(long long)DVH*DMODEL,
        M, DVH, DMODEL, pG,(long long)M*DVH, b_g, DVH, nullptr);
    gate_combine<<<(M*DVH/4 + 255)/256, 256>>>(pG, pO, pY);
    // final FC + bias + residual + pad zeroing
    gemm_mma<4,false,4><<<dim3(DMODEL/128, M/128, 1), blk, SMEM_SZ>>>(
        pY,0, w_fc,0, M, DMODEL, DVH, out,0, b_fc,0, enc);
}

// round 5
// speedup vs baseline: 5.7321x; 1.0724x over previous
#include <cuda_runtime.h>
#include <cuda_bf16.h>
#include <cstdint>

#define BATCH  8
#define LSEQ   1024
#define DMODEL 512
#define NHEAD  8
#define DKH    64
#define DVH    512

// ---------------- scratch (static device globals, zero-initialized) ---------
__device__ __align__(256) float g_Q [NHEAD*BATCH*LSEQ*DKH];   // [h][m][dk]
__device__ __align__(256) float g_K [NHEAD*BATCH*LSEQ*DKH];   // [h][m][dk]
__device__ __align__(256) float g_V [NHEAD*BATCH*LSEQ*DVH];   // [h][b][l][dv]
__device__ __align__(256) float g_S [67108864];               // [hb][q][k]
__device__ __align__(256) float g_O [NHEAD*BATCH*LSEQ*DVH];   // [h][m][dv]
__device__ __align__(256) float g_G [NHEAD*BATCH*LSEQ*DVH];
__device__ __align__(256) float g_Y [BATCH*LSEQ*DVH];
__device__ int   g_len[BATCH];

// ---------------- helpers ----------------------------------------------------
__device__ __forceinline__ uint32_t smem_u32(const void* p) {
    uint32_t a;
    asm("{ .reg .u64 t; cvta.to.shared.u64 t, %1; cvt.u32.u64 %0, t; }"
        : "=r"(a) : "l"(p));
    return a;
}
__device__ __forceinline__ void cp16(uint32_t s, const void* g) {
    asm volatile("cp.async.cg.shared.global [%0], [%1], 16;" :: "r"(s), "l"(g));
}
__device__ __forceinline__ void ldsm4(uint32_t& r0, uint32_t& r1,
                                      uint32_t& r2, uint32_t& r3, uint32_t a) {
    asm volatile("ldmatrix.sync.aligned.m8n8.x4.shared.b16 {%0,%1,%2,%3}, [%4];"
                 : "=r"(r0), "=r"(r1), "=r"(r2), "=r"(r3) : "r"(a));
}
__device__ __forceinline__ void mma_tf32(float& c0, float& c1, float& c2, float& c3,
                                         uint32_t a0, uint32_t a1, uint32_t a2, uint32_t a3,
                                         uint32_t b0, uint32_t b1) {
    asm volatile("mma.sync.aligned.m16n8k8.row.col.f32.tf32.tf32.f32 "
                 "{%0,%1,%2,%3}, {%4,%5,%6,%7}, {%8,%9}, {%0,%1,%2,%3};"
                 : "+f"(c0), "+f"(c1), "+f"(c2), "+f"(c3)
                 : "r"(a0), "r"(a1), "r"(a2), "r"(a3), "r"(b0), "r"(b1));
}

// ---------------- mask prep --------------------------------------------------
__global__ void prep_mask(const unsigned char* __restrict__ mask8) {
    __shared__ int s_violate;
    __shared__ int s_len[BATCH];
    const int t = threadIdx.x;
    if (t == 0) s_violate = 0;
    if (t < BATCH) s_len[t] = LSEQ;
    __syncthreads();
    for (int i = t; i < BATCH*LSEQ - 1; i += blockDim.x) {
        if ((i & (LSEQ-1)) != LSEQ-1) {
            if (mask8[i] != 0 && mask8[i+1] == 0) atomicOr(&s_violate, 1);
        }
    }
    __syncthreads();
    const bool is4 = (s_violate != 0);
    if (!is4) {
        for (int i = t; i < BATCH*LSEQ; i += blockDim.x)
            if (mask8[i] != 0) atomicMin(&s_len[i >> 10], i & (LSEQ-1));
    } else {
        const unsigned int* m32 = reinterpret_cast<const unsigned int*>(mask8);
        for (int i = t; i < BATCH*LSEQ; i += blockDim.x)
            if (m32[i] != 0) atomicMin(&s_len[i >> 10], i & (LSEQ-1));
    }
    __syncthreads();
    if (t < BATCH) g_len[t] = s_len[t];
}

// ---------------- tf32 mma.sync GEMM: C = A @ op(B) --------------------------
// BM=BN=128, BK=32, 256 threads (8 warps, 64x32 warp tiles), 3-stage pipeline.
// ldmatrix.x4 fragment loads (tf32-as-b16 trick) for A and [n][k]-layout B.
// MODE: 0 QK-proj store; 1 V-proj store; 2 plain; 3 +bias[batch]; 4 final;
//       5 fused QKV (blockIdx.x segments: [0,4)=Q, [4,8)=K, [8,40)=V)
// SKIP: 1 row-tile skip; 2 S-mode row+col skip; 3 PV row skip + K clamp;
//       4 final zero-fill padded rows.
#define ASTRIDE 36
#define BNSTRIDE 136
#define ABYTES  (128*ASTRIDE*4)     // 18432
#define STAGEB  (2*ABYTES)          // 36864
#define SMEM_SZ (3*STAGEB)          // 110592

template<int MODE, bool BKMAJOR, int SKIP>
__global__ void __launch_bounds__(256, 2)
gemm_mma(const float* __restrict__ A, long long sA,
         const float* __restrict__ Bm, long long sB,
         int M, int N, int K,
         float* __restrict__ C, long long sC,
         const float* __restrict__ bias, int sBias,
         const float* __restrict__ resid,
         const float* B2, const float* bias2, float* C2,
         const float* B3, const float* bias3, float* C3)
{
    extern __shared__ char dsm[];
    const int tid  = threadIdx.x;
    const int w    = tid >> 5;
    const int lane = tid & 31;
    const int wm   = w & 1;
    const int wn   = w >> 1;
    const int batch = blockIdx.z;
    const int bm = blockIdx.y * 128;

    const float* Bsrc = Bm;
    const float* biasp = bias;
    float* Cp = C;
    int bn = blockIdx.x * 128;
    int smode = MODE;
    if (MODE == 5) {
        const int bx = blockIdx.x;
        if (bx < 4)       { smode = 0; bn = bx * 128; }
        else if (bx < 8)  { smode = 0; bn = (bx-4) * 128; Bsrc = B2; biasp = bias2; Cp = C2; }
        else              { smode = 1; bn = (bx-8) * 128; Bsrc = B3; biasp = bias3; Cp = C3; }
    }

    int Keff = K;
    if (SKIP == 1) {
        if ((bm & (LSEQ-1)) >= g_len[bm >> 10]) return;
    } else if (SKIP == 2) {
        const int L = g_len[batch & (BATCH-1)];
        if (bm >= L || bn >= L) return;
    } else if (SKIP == 3) {
        const int L = g_len[batch & (BATCH-1)];
        if (bm >= L) return;
        Keff = (L + 31) & ~31;
    } else if (SKIP == 4) {
        if ((bm & (LSEQ-1)) >= g_len[bm >> 10]) {
            const float4 z = {0.f, 0.f, 0.f, 0.f};
            for (int i = tid; i < 128*32; i += 256) {
                const int r = i >> 5, c4 = i & 31;
                *reinterpret_cast<float4*>(&Cp[(long long)(bm + r)*N + bn + c4*4]) = z;
            }
            return;
        }
    }

    const float* Ab = A    + (long long)batch * sA;
    const float* Bb = Bsrc + (long long)batch * sB;
    const uint32_t smem0 = smem_u32(dsm);
    const int KC = Keff >> 5;

    auto load_stage = [&](int kc) {
        const int st = kc % 3;
        const uint32_t sa = smem0 + st * STAGEB;
        const uint32_t sb = sa + ABYTES;
        const int k0 = kc << 5;
        #pragma unroll
        for (int i = 0; i < 4; i++) {
            const int idx = tid + i * 256;
            const int row = idx >> 3, chk = idx & 7;
            cp16(sa + row*(ASTRIDE*4) + chk*16,
                 Ab + (long long)(bm + row) * K + k0 + chk*4);
        }
        if (!BKMAJOR) {
            #pragma unroll
            for (int i = 0; i < 4; i++) {
                const int idx = tid + i * 256;
                const int row = idx >> 3, chk = idx & 7;
                cp16(sb + row*(ASTRIDE*4) + chk*16,
                     Bb + (long long)(bn + row) * K + k0 + chk*4);
            }
        } else {
            #pragma unroll
            for (int i = 0; i < 4; i++) {
                const int idx = tid + i * 256;
                const int row = idx >> 5, chk = idx & 31;
                cp16(sb + row*(BNSTRIDE*4) + chk*16,
                     Bb + (long long)(k0 + row) * N + bn + chk*4);
            }
        }
        asm volatile("cp.async.commit_group;" ::: "memory");
    };

    float acc[4][4][4];
    #pragma unroll
    for (int i = 0; i < 4; i++)
        #pragma unroll
        for (int j = 0; j < 4; j++)
            #pragma unroll
            for (int q = 0; q < 4; q++) acc[i][j][q] = 0.f;

    load_stage(0);
    if (KC > 1) load_stage(1);

    // ldmatrix lane-derived offsets
    const int lrow_a  = lane & 15;                       // row 0..15 in 16-row tile
    const int lkoff_a = (lane >> 4) * 4;                 // k half: 0 or 4
    const int lrow_b  = (lane & 7) + ((lane >> 4) << 3); // n row 0..15
    const int lkoff_b = ((lane >> 3) & 1) * 4;           // k half: 0 or 4

    for (int kc = 0; kc < KC; kc++) {
        if (kc + 1 < KC) asm volatile("cp.async.wait_group 1;" ::: "memory");
        else             asm volatile("cp.async.wait_group 0;" ::: "memory");
        __syncthreads();
        if (kc + 2 < KC) load_stage(kc + 2);

        const int st = kc % 3;
        const uint32_t Abase = smem0 + st * STAGEB;
        const uint32_t Bbase = Abase + ABYTES;
        const float* Bf = (const float*)(dsm + st * STAGEB + ABYTES);

        #pragma unroll
        for (int ks = 0; ks < 4; ks++) {
            uint32_t af[4][4];
            #pragma unroll
            for (int mt = 0; mt < 4; mt++) {
                const uint32_t addr = Abase +
                    ((wm*64 + mt*16 + lrow_a)*ASTRIDE + ks*8 + lkoff_a) * 4;
                ldsm4(af[mt][0], af[mt][1], af[mt][2], af[mt][3], addr);
            }
            uint32_t bf[4][2];
            if (!BKMAJOR) {
                #pragma unroll
                for (int np = 0; np < 2; np++) {
                    const uint32_t addr = Bbase +
                        ((wn*32 + np*16 + lrow_b)*ASTRIDE + ks*8 + lkoff_b) * 4;
                    ldsm4(bf[np*2][0], bf[np*2][1], bf[np*2+1][0], bf[np*2+1][1], addr);
                }
            } else {
                const int k0 = ks*8 + (lane & 3);
                #pragma unroll
                for (int nt = 0; nt < 4; nt++) {
                    const int n = wn*32 + nt*8 + (lane >> 2);
                    bf[nt][0] = __float_as_uint(Bf[k0*BNSTRIDE + n]);
                    bf[nt][1] = __float_as_uint(Bf[(k0+4)*BNSTRIDE + n]);
                }
            }
            #pragma unroll
            for (int mt = 0; mt < 4; mt++)
                #pragma unroll
                for (int nt = 0; nt < 4; nt++)
                    mma_tf32(acc[mt][nt][0], acc[mt][nt][1], acc[mt][nt][2], acc[mt][nt][3],
                             af[mt][0], af[mt][1], af[mt][2], af[mt][3],
                             bf[nt][0], bf[nt][1]);
        }
    }

    // ---------------- epilogue (smode is compile-time for MODE!=5) -----------
    #pragma unroll
    for (int mt = 0; mt < 4; mt++) {
        const int r0 = bm + wm*64 + mt*16 + (lane >> 2);
        #pragma unroll
        for (int half = 0; half < 2; half++) {
            const int m = r0 + half*8;
            const int b_idx = m >> 10, l_idx = m & (LSEQ-1);
            #pragma unroll
            for (int nt = 0; nt < 4; nt++) {
                const int n = bn + wn*32 + nt*8 + (lane & 3)*2;
                float v0 = acc[mt][nt][half*2 + 0];
                float v1 = acc[mt][nt][half*2 + 1];
                if (smode == 0) {
                    const float2 bv = *reinterpret_cast<const float2*>(&biasp[n]);
                    v0 += bv.x; v1 += bv.y;
                    const int h = n >> 6, d = n & 63;
                    float2 o = {v0, v1};
                    *reinterpret_cast<float2*>(&Cp[((long long)h*(BATCH*LSEQ) + m)*DKH + d]) = o;
                } else if (smode == 1) {
                    const float2 bv = *reinterpret_cast<const float2*>(&biasp[n]);
                    v0 += bv.x; v1 += bv.y;
                    const int h = n >> 9, d = n & 511;
                    float2 o = {v0, v1};
                    *reinterpret_cast<float2*>(
                        &Cp[(long long)h*(BATCH*LSEQ)*DVH + (long long)m*DVH + d]) = o;
                } else if (smode == 2) {
                    float2 o = {v0, v1};
                    *reinterpret_cast<float2*>(
                        &Cp[(long long)batch*sC + (long long)m*N + n]) = o;
                } else if (smode == 3) {
                    const float2 bv = *reinterpret_cast<const float2*>(
                        &biasp[(long long)batch*sBias + n]);
                    float2 o = {v0 + bv.x, v1 + bv.y};
                    *reinterpret_cast<float2*>(
                        &Cp[(long long)batch*sC + (long long)m*N + n]) = o;
                } else { // smode 4
                    float2 o;
                    if (l_idx >= g_len[b_idx]) { o.x = 0.f; o.y = 0.f; }
                    else {
                        const float2 bv = *reinterpret_cast<const float2*>(&biasp[n]);
                        const float2 rv = *reinterpret_cast<const float2*>(
                            &resid[(long long)m*N + n]);
                        o.x = v0 + bv.x + rv.x;
                        o.y = v1 + bv.y + rv.y;
                    }
                    *reinterpret_cast<float2*>(&Cp[(long long)m*N + n]) = o;
                }
            }
        }
    }
}

// ---------------- masked row softmax, single pass, row in registers ----------
__global__ void softmax_rows(float* __restrict__ S) {
    const int hb  = blockIdx.y;
    const int len = g_len[hb & (BATCH-1)];
    const int q   = blockIdx.x;
    if (q >= len) return;
    float4* row = reinterpret_cast<float4*>(S + ((long long)hb * LSEQ + q) * LSEQ);

    const int t = threadIdx.x;
    const float4 v = row[t];
    const int j0 = t * 4;
    const float NEG = -1e30f;
    float x0 = (j0+0 < len) ? v.x : NEG;
    float x1 = (j0+1 < len) ? v.y : NEG;
    float x2 = (j0+2 < len) ? v.z : NEG;
    float x3 = (j0+3 < len) ? v.w : NEG;

    __shared__ float rmax[8], rsum[8];
    float mx = fmaxf(fmaxf(x0, x1), fmaxf(x2, x3));
    #pragma unroll
    for (int o = 16; o; o >>= 1) mx = fmaxf(mx, __shfl_xor_sync(~0u, mx, o));
    if ((t & 31) == 0) rmax[t >> 5] = mx;
    __syncthreads();
    mx = rmax[0];
    #pragma unroll
    for (int i = 1; i < 8; i++) mx = fmaxf(mx, rmax[i]);
    mx *= 0.125f;

    const float e0 = __expf(x0*0.125f - mx);
    const float e1 = __expf(x1*0.125f - mx);
    const float e2 = __expf(x2*0.125f - mx);
    const float e3 = __expf(x3*0.125f - mx);
    float s = e0 + e1 + e2 + e3;
    #pragma unroll
    for (int o = 16; o; o >>= 1) s += __shfl_xor_sync(~0u, s, o);
    if ((t & 31) == 0) rsum[t >> 5] = s;
    __syncthreads();
    s = rsum[0];
    #pragma unroll
    for (int i = 1; i < 8; i++) s += rsum[i];
    const float inv = 1.f / s;

    float4 o = {e0*inv, e1*inv, e2*inv, e3*inv};
    row[t] = o;
}

// ---------------- head-gate softmax + weighted combine (float4) --------------
__global__ void gate_combine(const float* __restrict__ G,
                             const float* __restrict__ O,
                             float* __restrict__ Y) {
    const int HS4 = BATCH*LSEQ*DVH/4;
    const int i = blockIdx.x * blockDim.x + threadIdx.x;
    if (i >= HS4) return;
    const int m = i >> 7;
    if ((m & (LSEQ-1)) >= g_len[m >> 10]) return;

    const float4* G4 = reinterpret_cast<const float4*>(G);
    const float4* O4 = reinterpret_cast<const float4*>(O);
    float4 g[NHEAD];
    #pragma unroll
    for (int h = 0; h < NHEAD; h++) g[h] = G4[(long long)h*HS4 + i];
    float4 mx = g[0];
    #pragma unroll
    for (int h = 1; h < NHEAD; h++) {
        mx.x = fmaxf(mx.x, g[h].x); mx.y = fmaxf(mx.y, g[h].y);
        mx.z = fmaxf(mx.z, g[h].z); mx.w = fmaxf(mx.w, g[h].w);
    }
    float4 acc = {0,0,0,0}, ssum = {0,0,0,0};
    #pragma unroll
    for (int h = 0; h < NHEAD; h++) {
        const float4 o = O4[(long long)h*HS4 + i];
        const float ex = __expf(g[h].x - mx.x), ey = __expf(g[h].y - mx.y);
        const float ez = __expf(g[h].z - mx.z), ew = __expf(g[h].w - mx.w);
        ssum.x += ex; ssum.y += ey; ssum.z += ez; ssum.w += ew;
        acc.x += ex*o.x; acc.y += ey*o.y; acc.z += ez*o.z; acc.w += ew*o.w;
    }
    float4 y = {acc.x/ssum.x, acc.y/ssum.y, acc.z/ssum.z, acc.w/ssum.w};
    reinterpret_cast<float4*>(Y)[i] = y;
}

// ---------------- launch ------------------------------------------------------
extern "C" void kernel_launch(void* const* d_in, const int* in_sizes, int n_in,
                              void* d_out, int out_size) {
    const float*         enc  = (const float*)d_in[0];
    const unsigned char* npm  = (const unsigned char*)d_in[1];
    const float* w_q  = (const float*)d_in[3];
    const float* b_q  = (const float*)d_in[4];
    const float* w_k  = (const float*)d_in[5];
    const float* b_k  = (const float*)d_in[6];
    const float* w_v  = (const float*)d_in[7];
    const float* b_v  = (const float*)d_in[8];
    const float* w_g  = (const float*)d_in[9];
    const float* b_g  = (const float*)d_in[10];
    const float* w_fc = (const float*)d_in[11];
    const float* b_fc = (const float*)d_in[12];
    float* out = (float*)d_out;

    float *pQ,*pK,*pV,*pS,*pO,*pG,*pY;
    cudaGetSymbolAddress((void**)&pQ, g_Q);
    cudaGetSymbolAddress((void**)&pK, g_K);
    cudaGetSymbolAddress((void**)&pV, g_V);
    cudaGetSymbolAddress((void**)&pS, g_S);
    cudaGetSymbolAddress((void**)&pO, g_O);
    cudaGetSymbolAddress((void**)&pG, g_G);
    cudaGetSymbolAddress((void**)&pY, g_Y);

    cudaFuncSetAttribute(gemm_mma<5,false,1>, cudaFuncAttributeMaxDynamicSharedMemorySize, SMEM_SZ);
    cudaFuncSetAttribute(gemm_mma<2,false,2>, cudaFuncAttributeMaxDynamicSharedMemorySize, SMEM_SZ);
    cudaFuncSetAttribute(gemm_mma<2,true ,3>, cudaFuncAttributeMaxDynamicSharedMemorySize, SMEM_SZ);
    cudaFuncSetAttribute(gemm_mma<3,false,1>, cudaFuncAttributeMaxDynamicSharedMemorySize, SMEM_SZ);
    cudaFuncSetAttribute(gemm_mma<4,false,4>, cudaFuncAttributeMaxDynamicSharedMemorySize, SMEM_SZ);

    const int M = BATCH * LSEQ;      // 8192
    dim3 blk(256);

    prep_mask<<<1, 256>>>(npm);

    // Fused QKV projections: one launch, 40 column segments
    gemm_mma<5,false,1><<<dim3(40, M/128, 1), blk, SMEM_SZ>>>(
        enc,0, w_q,0, M, NHEAD*DKH, DMODEL, pQ,0, b_q,0, nullptr,
        w_k, b_k, pK, w_v, b_v, pV);
    // S = Q @ K^T per (h,b)
    gemm_mma<2,false,2><<<dim3(LSEQ/128, LSEQ/128, NHEAD*BATCH), blk, SMEM_SZ>>>(
        pQ,(long long)LSEQ*DKH, pK,(long long)LSEQ*DKH,
        LSEQ, LSEQ, DKH, pS,(long long)LSEQ*LSEQ, nullptr,0, nullptr,
        nullptr,nullptr,nullptr, nullptr,nullptr,nullptr);
    softmax_rows<<<dim3(LSEQ, NHEAD*BATCH), 256>>>(pS);
    // O = P @ V
    gemm_mma<2,true,3><<<dim3(DVH/128, LSEQ/128, NHEAD*BATCH), blk, SMEM_SZ>>>(
        pS,(long long)LSEQ*LSEQ, pV,(long long)LSEQ*DVH,
        LSEQ, DVH, LSEQ, pO,(long long)LSEQ*DVH, nullptr,0, nullptr,
        nullptr,nullptr,nullptr, nullptr,nullptr,nullptr);
    // gate logits
    gemm_mma<3,false,1><<<dim3(DVH/128, M/128, NHEAD), blk, SMEM_SZ>>>(
        pO,(long long)M*DVH, w_g,(long long)DVH*DMODEL,
        M, DVH, DMODEL, pG,(long long)M*DVH, b_g, DVH, nullptr,
        nullptr,nullptr,nullptr, nullptr,nullptr,nullptr);
    gate_combine<<<(M*DVH/4 + 255)/256, 256>>>(pG, pO, pY);
    // final FC + bias + residual + pad zeroing
    gemm_mma<4,false,4><<<dim3(DMODEL/128, M/128, 1), blk, SMEM_SZ>>>(
        pY,0, w_fc,0, M, DMODEL, DVH, out,0, b_fc,0, enc,
        nullptr,nullptr,nullptr, nullptr,nullptr,nullptr);
}

// round 7
// speedup vs baseline: 5.7429x; 1.0019x over previous
#include <cuda_runtime.h>
#include <cuda_bf16.h>
#include <cstdint>

#define BATCH  8
#define LSEQ   1024
#define DMODEL 512
#define NHEAD  8
#define DKH    64
#define DVH    512

// ---------------- scratch (static device globals, zero-initialized) ---------
__device__ __align__(256) float g_Q [NHEAD*BATCH*LSEQ*DKH];   // [h][m][dk]
__device__ __align__(256) float g_K [NHEAD*BATCH*LSEQ*DKH];   // [h][m][dk]
__device__ __align__(256) float g_Vt[NHEAD*BATCH*DVH*LSEQ];   // [h][b][dv][l]
__device__ __align__(256) float g_S [67108864];               // [hb][q][k]
__device__ __align__(256) float g_O [NHEAD*BATCH*LSEQ*DVH];   // [h][m][dv]
__device__ __align__(256) float g_G [NHEAD*BATCH*LSEQ*DVH];
__device__ __align__(256) float g_Y [BATCH*LSEQ*DVH];
__device__ int   g_len[BATCH];

// ---------------- helpers ----------------------------------------------------
__device__ __forceinline__ uint32_t smem_u32(const void* p) {
    uint32_t a;
    asm("{ .reg .u64 t; cvta.to.shared.u64 t, %1; cvt.u32.u64 %0, t; }"
        : "=r"(a) : "l"(p));
    return a;
}
__device__ __forceinline__ void cp16(uint32_t s, const void* g) {
    asm volatile("cp.async.cg.shared.global [%0], [%1], 16;" :: "r"(s), "l"(g));
}
__device__ __forceinline__ void ldsm4(uint32_t& r0, uint32_t& r1,
                                      uint32_t& r2, uint32_t& r3, uint32_t a) {
    asm volatile("ldmatrix.sync.aligned.m8n8.x4.shared.b16 {%0,%1,%2,%3}, [%4];"
                 : "=r"(r0), "=r"(r1), "=r"(r2), "=r"(r3) : "r"(a));
}
__device__ __forceinline__ void mma_tf32(float& c0, float& c1, float& c2, float& c3,
                                         uint32_t a0, uint32_t a1, uint32_t a2, uint32_t a3,
                                         uint32_t b0, uint32_t b1) {
    asm volatile("mma.sync.aligned.m16n8k8.row.col.f32.tf32.tf32.f32 "
                 "{%0,%1,%2,%3}, {%4,%5,%6,%7}, {%8,%9}, {%0,%1,%2,%3};"
                 : "+f"(c0), "+f"(c1), "+f"(c2), "+f"(c3)
                 : "r"(a0), "r"(a1), "r"(a2), "r"(a3), "r"(b0), "r"(b1));
}

// ---------------- mask prep --------------------------------------------------
__global__ void prep_mask(const unsigned char* __restrict__ mask8) {
    __shared__ int s_violate;
    __shared__ int s_len[BATCH];
    const int t = threadIdx.x;
    if (t == 0) s_violate = 0;
    if (t < BATCH) s_len[t] = LSEQ;
    __syncthreads();
    for (int i = t; i < BATCH*LSEQ - 1; i += blockDim.x) {
        if ((i & (LSEQ-1)) != LSEQ-1) {
            if (mask8[i] != 0 && mask8[i+1] == 0) atomicOr(&s_violate, 1);
        }
    }
    __syncthreads();
    const bool is4 = (s_violate != 0);
    if (!is4) {
        for (int i = t; i < BATCH*LSEQ; i += blockDim.x)
            if (mask8[i] != 0) atomicMin(&s_len[i >> 10], i & (LSEQ-1));
    } else {
        const unsigned int* m32 = reinterpret_cast<const unsigned int*>(mask8);
        for (int i = t; i < BATCH*LSEQ; i += blockDim.x)
            if (m32[i] != 0) atomicMin(&s_len[i >> 10], i & (LSEQ-1));
    }
    __syncthreads();
    if (t < BATCH) g_len[t] = s_len[t];
}

// ---------------- tf32 mma.sync GEMM: C = A @ B^T ----------------------------
// BM=BN=128, BK=32, 256 threads (8 warps, 64x32 warp tiles), 3-stage pipeline,
// ldmatrix.x4 fragment loads for both operands.
// MODE: 2 plain batched; 3 +bias[batch*sBias+n] batched; 4 final (+bias+resid,
//       zero padded); 5 fused QKV (bx<4 Q, bx<8 K -> mode0 store; else V ->
//       transposed smem-staged store into Vt[h][b][dv][l]).
// SKIP: 1 row-tile skip; 2 S-mode row+col skip; 3 PV row skip + K clamp;
//       4 final zero-fill padded rows.
#define ASTRIDE 36
#define ABYTES  (128*ASTRIDE*4)     // 18432
#define STAGEB  (2*ABYTES)          // 36864
#define SMEM_SZ (3*STAGEB)          // 110592
#define TSTRIDE 133                 // transpose staging stride (floats)

template<int MODE, int SKIP>
__global__ void __launch_bounds__(256, 2)
gemm_mma(const float* __restrict__ A, long long sA,
         const float* __restrict__ Bm, long long sB,
         int M, int N, int K,
         float* __restrict__ C, long long sC,
         const float* __restrict__ bias, int sBias,
         const float* __restrict__ resid,
         const float* B2, const float* bias2, float* C2,
         const float* B3, const float* bias3, float* C3)
{
    extern __shared__ char dsm[];
    const int tid  = threadIdx.x;
    const int w    = tid >> 5;
    const int lane = tid & 31;
    const int wm   = w & 1;
    const int wn   = w >> 1;
    const int batch = blockIdx.z;
    const int bm = blockIdx.y * 128;

    const float* Bsrc = Bm;
    const float* biasp = bias;
    float* Cp = C;
    int bn = blockIdx.x * 128;
    int smode = MODE;                 // 0 = QK store, 6 = V transposed store
    if (MODE == 5) {
        const int bx = blockIdx.x;
        if (bx < 4)      { smode = 0; bn = bx * 128; }
        else if (bx < 8) { smode = 0; bn = (bx-4) * 128; Bsrc = B2; biasp = bias2; Cp = C2; }
        else             { smode = 6; bn = (bx-8) * 128; Bsrc = B3; biasp = bias3; Cp = C3; }
    }

    int Keff = K;
    if (SKIP == 1) {
        if ((bm & (LSEQ-1)) >= g_len[bm >> 10]) return;
    } else if (SKIP == 2) {
        const int L = g_len[batch & (BATCH-1)];
        if (bm >= L || bn >= L) return;
    } else if (SKIP == 3) {
        const int L = g_len[batch & (BATCH-1)];
        if (bm >= L) return;
        Keff = (L + 31) & ~31;
    } else if (SKIP == 4) {
        if ((bm & (LSEQ-1)) >= g_len[bm >> 10]) {
            const float4 z = {0.f, 0.f, 0.f, 0.f};
            for (int i = tid; i < 128*32; i += 256) {
                const int r = i >> 5, c4 = i & 31;
                *reinterpret_cast<float4*>(&Cp[(long long)(bm + r)*N + bn + c4*4]) = z;
            }
            return;
        }
    }

    const float* Ab = A    + (long long)batch * sA;
    const float* Bb = Bsrc + (long long)batch * sB;
    const uint32_t smem0 = smem_u32(dsm);
    const int KC = Keff >> 5;

    auto load_stage = [&](int kc) {
        const int st = kc % 3;
        const uint32_t sa = smem0 + st * STAGEB;
        const uint32_t sb = sa + ABYTES;
        const int k0 = kc << 5;
        #pragma unroll
        for (int i = 0; i < 4; i++) {
            const int idx = tid + i * 256;
            const int row = idx >> 3, chk = idx & 7;
            cp16(sa + row*(ASTRIDE*4) + chk*16,
                 Ab + (long long)(bm + row) * K + k0 + chk*4);
        }
        #pragma unroll
        for (int i = 0; i < 4; i++) {
            const int idx = tid + i * 256;
            const int row = idx >> 3, chk = idx & 7;
            cp16(sb + row*(ASTRIDE*4) + chk*16,
                 Bb + (long long)(bn + row) * K + k0 + chk*4);
        }
        asm volatile("cp.async.commit_group;" ::: "memory");
    };

    float acc[4][4][4];
    #pragma unroll
    for (int i = 0; i < 4; i++)
        #pragma unroll
        for (int j = 0; j < 4; j++)
            #pragma unroll
            for (int q = 0; q < 4; q++) acc[i][j][q] = 0.f;

    load_stage(0);
    if (KC > 1) load_stage(1);

    const int lrow_a  = lane & 15;
    const int lkoff_a = (lane >> 4) * 4;
    const int lrow_b  = (lane & 7) + ((lane >> 4) << 3);
    const int lkoff_b = ((lane >> 3) & 1) * 4;

    for (int kc = 0; kc < KC; kc++) {
        if (kc + 1 < KC) asm volatile("cp.async.wait_group 1;" ::: "memory");
        else             asm volatile("cp.async.wait_group 0;" ::: "memory");
        __syncthreads();
        if (kc + 2 < KC) load_stage(kc + 2);

        const int st = kc % 3;
        const uint32_t Abase = smem0 + st * STAGEB;
        const uint32_t Bbase = Abase + ABYTES;

        #pragma unroll
        for (int ks = 0; ks < 4; ks++) {
            uint32_t af[4][4];
            #pragma unroll
            for (int mt = 0; mt < 4; mt++) {
                const uint32_t addr = Abase +
                    ((wm*64 + mt*16 + lrow_a)*ASTRIDE + ks*8 + lkoff_a) * 4;
                ldsm4(af[mt][0], af[mt][1], af[mt][2], af[mt][3], addr);
            }
            uint32_t bf[4][2];
            #pragma unroll
            for (int np = 0; np < 2; np++) {
                const uint32_t addr = Bbase +
                    ((wn*32 + np*16 + lrow_b)*ASTRIDE + ks*8 + lkoff_b) * 4;
                ldsm4(bf[np*2][0], bf[np*2][1], bf[np*2+1][0], bf[np*2+1][1], addr);
            }
            #pragma unroll
            for (int mt = 0; mt < 4; mt++)
                #pragma unroll
                for (int nt = 0; nt < 4; nt++)
                    mma_tf32(acc[mt][nt][0], acc[mt][nt][1], acc[mt][nt][2], acc[mt][nt][3],
                             af[mt][0], af[mt][1], af[mt][2], af[mt][3],
                             bf[nt][0], bf[nt][1]);
        }
    }

    // ---------------- V transposed store via smem staging (smode 6) ----------
    if (MODE == 5 && smode == 6) {
        __syncthreads();                              // pipeline smem now free
        float* stg = reinterpret_cast<float*>(dsm);   // [128 m][TSTRIDE]
        #pragma unroll
        for (int mt = 0; mt < 4; mt++) {
            #pragma unroll
            for (int half = 0; half < 2; half++) {
                const int ml = wm*64 + mt*16 + (lane >> 2) + half*8;
                #pragma unroll
                for (int nt = 0; nt < 4; nt++) {
                    const int nl = wn*32 + nt*8 + (lane & 3)*2;
                    const float2 bv = *reinterpret_cast<const float2*>(&biasp[bn + nl]);
                    stg[ml*TSTRIDE + nl]     = acc[mt][nt][half*2 + 0] + bv.x;
                    stg[ml*TSTRIDE + nl + 1] = acc[mt][nt][half*2 + 1] + bv.y;
                }
            }
        }
        __syncthreads();
        const int h = bn >> 9, dv0 = bn & 511;
        const int b = bm >> 10, l0 = bm & (LSEQ-1);
        float* Vt = Cp + (((long long)h*BATCH + b)*DVH + dv0)*LSEQ + l0;
        #pragma unroll
        for (int i = 0; i < 16; i++) {
            const int idx = tid + i*256;
            const int dv = idx >> 5, c4 = idx & 31;
            float4 o;
            o.x = stg[(c4*4+0)*TSTRIDE + dv];
            o.y = stg[(c4*4+1)*TSTRIDE + dv];
            o.z = stg[(c4*4+2)*TSTRIDE + dv];
            o.w = stg[(c4*4+3)*TSTRIDE + dv];
            *reinterpret_cast<float4*>(&Vt[(long long)dv*LSEQ + c4*4]) = o;
        }
        return;
    }

    // ---------------- generic epilogue ----------------------------------------
    #pragma unroll
    for (int mt = 0; mt < 4; mt++) {
        const int r0 = bm + wm*64 + mt*16 + (lane >> 2);
        #pragma unroll
        for (int half = 0; half < 2; half++) {
            const int m = r0 + half*8;
            const int b_idx = m >> 10, l_idx = m & (LSEQ-1);
            #pragma unroll
            for (int nt = 0; nt < 4; nt++) {
                const int n = bn + wn*32 + nt*8 + (lane & 3)*2;
                float v0 = acc[mt][nt][half*2 + 0];
                float v1 = acc[mt][nt][half*2 + 1];
                if (MODE == 5) {      // QK projection store
                    const float2 bv = *reinterpret_cast<const float2*>(&biasp[n]);
                    v0 += bv.x; v1 += bv.y;
                    const int h = n >> 6, d = n & 63;
                    float2 o = {v0, v1};
                    *reinterpret_cast<float2*>(&Cp[((long long)h*(BATCH*LSEQ) + m)*DKH + d]) = o;
                } else if (MODE == 2) {
                    float2 o = {v0, v1};
                    *reinterpret_cast<float2*>(
                        &Cp[(long long)batch*sC + (long long)m*N + n]) = o;
                } else if (MODE == 3) {
                    const float2 bv = *reinterpret_cast<const float2*>(
                        &biasp[(long long)batch*sBias + n]);
                    float2 o = {v0 + bv.x, v1 + bv.y};
                    *reinterpret_cast<float2*>(
                        &Cp[(long long)batch*sC + (long long)m*N + n]) = o;
                } else { // MODE 4
                    float2 o;
                    if (l_idx >= g_len[b_idx]) { o.x = 0.f; o.y = 0.f; }
                    else {
                        const float2 bv = *reinterpret_cast<const float2*>(&biasp[n]);
                        const float2 rv = *reinterpret_cast<const float2*>(
                            &resid[(long long)m*N + n]);
                        o.x = v0 + bv.x + rv.x;
                        o.y = v1 + bv.y + rv.y;
                    }
                    *reinterpret_cast<float2*>(&Cp[(long long)m*N + n]) = o;
                }
            }
        }
    }
}

// ---------------- masked row softmax, single pass -----------------------------
__global__ void softmax_rows(float* __restrict__ S) {
    const int hb  = blockIdx.y;
    const int len = g_len[hb & (BATCH-1)];
    const int q   = blockIdx.x;
    if (q >= len) return;
    float4* row = reinterpret_cast<float4*>(S + ((long long)hb * LSEQ + q) * LSEQ);

    const int t = threadIdx.x;
    const float4 v = row[t];
    const int j0 = t * 4;
    const float NEG = -1e30f;
    float x0 = (j0+0 < len) ? v.x : NEG;
    float x1 = (j0+1 < len) ? v.y : NEG;
    float x2 = (j0+2 < len) ? v.z : NEG;
    float x3 = (j0+3 < len) ? v.w : NEG;

    __shared__ float rmax[8], rsum[8];
    float mx = fmaxf(fmaxf(x0, x1), fmaxf(x2, x3));
    #pragma unroll
    for (int o = 16; o; o >>= 1) mx = fmaxf(mx, __shfl_xor_sync(~0u, mx, o));
    if ((t & 31) == 0) rmax[t >> 5] = mx;
    __syncthreads();
    mx = rmax[0];
    #pragma unroll
    for (int i = 1; i < 8; i++) mx = fmaxf(mx, rmax[i]);
    mx *= 0.125f;

    const float e0 = __expf(x0*0.125f - mx);
    const float e1 = __expf(x1*0.125f - mx);
    const float e2 = __expf(x2*0.125f - mx);
    const float e3 = __expf(x3*0.125f - mx);
    float s = e0 + e1 + e2 + e3;
    #pragma unroll
    for (int o = 16; o; o >>= 1) s += __shfl_xor_sync(~0u, s, o);
    if ((t & 31) == 0) rsum[t >> 5] = s;
    __syncthreads();
    s = rsum[0];
    #pragma unroll
    for (int i = 1; i < 8; i++) s += rsum[i];
    const float inv = 1.f / s;

    float4 o = {e0*inv, e1*inv, e2*inv, e3*inv};
    row[t] = o;
}

// ---------------- head-gate softmax + weighted combine (float4) ---------------
__global__ void gate_combine(const float* __restrict__ G,
                             const float* __restrict__ O,
                             float* __restrict__ Y) {
    const int HS4 = BATCH*LSEQ*DVH/4;
    const int i = blockIdx.x * blockDim.x + threadIdx.x;
    if (i >= HS4) return;
    const int m = i >> 7;
    if ((m & (LSEQ-1)) >= g_len[m >> 10]) return;

    const float4* G4 = reinterpret_cast<const float4*>(G);
    const float4* O4 = reinterpret_cast<const float4*>(O);
    float4 g[NHEAD];
    #pragma unroll
    for (int h = 0; h < NHEAD; h++) g[h] = G4[(long long)h*HS4 + i];
    float4 mx = g[0];
    #pragma unroll
    for (int h = 1; h < NHEAD; h++) {
        mx.x = fmaxf(mx.x, g[h].x); mx.y = fmaxf(mx.y, g[h].y);
        mx.z = fmaxf(mx.z, g[h].z); mx.w = fmaxf(mx.w, g[h].w);
    }
    float4 acc = {0,0,0,0}, ssum = {0,0,0,0};
    #pragma unroll
    for (int h = 0; h < NHEAD; h++) {
        const float4 o = O4[(long long)h*HS4 + i];
        const float ex = __expf(g[h].x - mx.x), ey = __expf(g[h].y - mx.y);
        const float ez = __expf(g[h].z - mx.z), ew = __expf(g[h].w - mx.w);
        ssum.x += ex; ssum.y += ey; ssum.z += ez; ssum.w += ew;
        acc.x += ex*o.x; acc.y += ey*o.y; acc.z += ez*o.z; acc.w += ew*o.w;
    }
    float4 y = {acc.x/ssum.x, acc.y/ssum.y, acc.z/ssum.z, acc.w/ssum.w};
    reinterpret_cast<float4*>(Y)[i] = y;
}

// ---------------- launch ------------------------------------------------------
extern "C" void kernel_launch(void* const* d_in, const int* in_sizes, int n_in,
                              void* d_out, int out_size) {
    const float*         enc  = (const float*)d_in[0];
    const unsigned char* npm  = (const unsigned char*)d_in[1];
    const float* w_q  = (const float*)d_in[3];
    const float* b_q  = (const float*)d_in[4];
    const float* w_k  = (const float*)d_in[5];
    const float* b_k  = (const float*)d_in[6];
    const float* w_v  = (const float*)d_in[7];
    const float* b_v  = (const float*)d_in[8];
    const float* w_g  = (const float*)d_in[9];
    const float* b_g  = (const float*)d_in[10];
    const float* w_fc = (const float*)d_in[11];
    const float* b_fc = (const float*)d_in[12];
    float* out = (float*)d_out;

    float *pQ,*pK,*pVt,*pS,*pO,*pG,*pY;
    cudaGetSymbolAddress((void**)&pQ,  g_Q);
    cudaGetSymbolAddress((void**)&pK,  g_K);
    cudaGetSymbolAddress((void**)&pVt, g_Vt);
    cudaGetSymbolAddress((void**)&pS,  g_S);
    cudaGetSymbolAddress((void**)&pO,  g_O);
    cudaGetSymbolAddress((void**)&pG,  g_G);
    cudaGetSymbolAddress((void**)&pY,  g_Y);

    cudaFuncSetAttribute(gemm_mma<5,1>, cudaFuncAttributeMaxDynamicSharedMemorySize, SMEM_SZ);
    cudaFuncSetAttribute(gemm_mma<2,2>, cudaFuncAttributeMaxDynamicSharedMemorySize, SMEM_SZ);
    cudaFuncSetAttribute(gemm_mma<2,3>, cudaFuncAttributeMaxDynamicSharedMemorySize, SMEM_SZ);
    cudaFuncSetAttribute(gemm_mma<3,1>, cudaFuncAttributeMaxDynamicSharedMemorySize, SMEM_SZ);
    cudaFuncSetAttribute(gemm_mma<4,4>, cudaFuncAttributeMaxDynamicSharedMemorySize, SMEM_SZ);

    const int M = BATCH * LSEQ;      // 8192
    dim3 blk(256);

    prep_mask<<<1, 256>>>(npm);

    // Fused Q/K/V projections: one launch, 40 column segments.
    // Q,K -> [h][m][dk]; V -> transposed Vt[h][b][dv][l] via smem staging.
    gemm_mma<5,1><<<dim3(40, M/128, 1), blk, SMEM_SZ>>>(
        enc,0, w_q,0, M, NHEAD*DKH, DMODEL, pQ,0, b_q,0, nullptr,
        w_k, b_k, pK, w_v, b_v, pVt);
    // S = Q @ K^T per (h,b), masked tiles skipped
    gemm_mma<2,2><<<dim3(LSEQ/128, LSEQ/128, NHEAD*BATCH), blk, SMEM_SZ>>>(
        pQ,(long long)LSEQ*DKH, pK,(long long)LSEQ*DKH,
        LSEQ, LSEQ, DKH, pS,(long long)LSEQ*LSEQ, nullptr,0, nullptr,
        nullptr,nullptr,nullptr, nullptr,nullptr,nullptr);
    softmax_rows<<<dim3(LSEQ, NHEAD*BATCH), 256>>>(pS);
    // O = P @ Vt^T per (h,b) — both operands via ldmatrix, K clamped to len
    gemm_mma<2,3><<<dim3(DVH/128, LSEQ/128, NHEAD*BATCH), blk, SMEM_SZ>>>(
        pS,(long long)LSEQ*LSEQ, pVt,(long long)DVH*LSEQ,
        LSEQ, DVH, LSEQ, pO,(long long)LSEQ*DVH, nullptr,0, nullptr,
        nullptr,nullptr,nullptr, nullptr,nullptr,nullptr);
    // gate logits: batched over heads, per-head bias
    gemm_mma<3,1><<<dim3(DVH/128, M/128, NHEAD), blk, SMEM_SZ>>>(
        pO,(long long)M*DVH, w_g,(long long)DVH*DMODEL,
        M, DVH, DMODEL, pG,(long long)M*DVH, b_g, DVH, nullptr,
        nullptr,nullptr,nullptr, nullptr,nullptr,nullptr);
    gate_combine<<<(M*DVH/4 + 255)/256, 256>>>(pG, pO, pY);
    // final FC + bias + residual + pad zeroing
    gemm_mma<4,4><<<dim3(DMODEL/128, M/128, 1), blk, SMEM_SZ>>>(
        pY,0, w_fc,0, M, DMODEL, DVH, out,0, b_fc,0, enc,
        nullptr,nullptr,nullptr, nullptr,nullptr,nullptr);
}

// round 8
// speedup vs baseline: 9.2007x; 1.6021x over previous
#include <cuda_runtime.h>
#include <cuda_fp16.h>
#include <cstdint>

#define BATCH  8
#define LSEQ   1024
#define DMODEL 512
#define NHEAD  8
#define DKH    64
#define DVH    512
#define MTOT   (BATCH*LSEQ)

// ---------------- scratch (static device globals, zero-initialized) ---------
// Padded regions (rows/cols >= len[b]) are never written and stay 0.
__device__ __align__(256) __half g_ench[MTOT*DMODEL];
__device__ __align__(256) __half g_Wqh [DMODEL*DMODEL];
__device__ __align__(256) __half g_Wkh [DMODEL*DMODEL];
__device__ __align__(256) __half g_Wvh [NHEAD*DVH*DMODEL];
__device__ __align__(256) __half g_Wgh [NHEAD*DVH*DMODEL];
__device__ __align__(256) __half g_Wfch[DMODEL*DVH];
__device__ __align__(256) __half g_Q [NHEAD*MTOT*DKH];     // [h][m][dk]
__device__ __align__(256) __half g_K [NHEAD*MTOT*DKH];     // [h][m][dk]
__device__ __align__(256) __half g_Vt[NHEAD*BATCH*DVH*LSEQ]; // [h][b][dv][l]
__device__ __align__(256) float  g_S [67108864];           // [hb][q][k] fp32
__device__ __align__(256) __half g_P [67108864];           // softmax(S) fp16
__device__ __align__(256) __half g_O [NHEAD*MTOT*DVH];     // [h][m][dv]
__device__ __align__(256) __half g_G [NHEAD*MTOT*DVH];
__device__ __align__(256) __half g_Y [MTOT*DVH];
__device__ int   g_len[BATCH];

// ---------------- helpers ----------------------------------------------------
__device__ __forceinline__ uint32_t smem_u32(const void* p) {
    uint32_t a;
    asm("{ .reg .u64 t; cvta.to.shared.u64 t, %1; cvt.u32.u64 %0, t; }"
        : "=r"(a) : "l"(p));
    return a;
}
__device__ __forceinline__ void cp16(uint32_t s, const void* g) {
    asm volatile("cp.async.cg.shared.global [%0], [%1], 16;" :: "r"(s), "l"(g));
}
__device__ __forceinline__ void ldsm4(uint32_t& r0, uint32_t& r1,
                                      uint32_t& r2, uint32_t& r3, uint32_t a) {
    asm volatile("ldmatrix.sync.aligned.m8n8.x4.shared.b16 {%0,%1,%2,%3}, [%4];"
                 : "=r"(r0), "=r"(r1), "=r"(r2), "=r"(r3) : "r"(a));
}
__device__ __forceinline__ void mma_f16(float& c0, float& c1, float& c2, float& c3,
                                        uint32_t a0, uint32_t a1, uint32_t a2, uint32_t a3,
                                        uint32_t b0, uint32_t b1) {
    asm volatile("mma.sync.aligned.m16n8k16.row.col.f32.f16.f16.f32 "
                 "{%0,%1,%2,%3}, {%4,%5,%6,%7}, {%8,%9}, {%0,%1,%2,%3};"
                 : "+f"(c0), "+f"(c1), "+f"(c2), "+f"(c3)
                 : "r"(a0), "r"(a1), "r"(a2), "r"(a3), "r"(b0), "r"(b1));
}

// ---------------- fp32 -> fp16 conversion of enc + weights -------------------
#define N_ENC (MTOT*DMODEL)                 // 4194304
#define N_WQ  (DMODEL*DMODEL)               // 262144
#define N_WV  (NHEAD*DVH*DMODEL)            // 2097152
__global__ void convert_inputs(const float* __restrict__ enc,
                               const float* __restrict__ wq,
                               const float* __restrict__ wk,
                               const float* __restrict__ wv,
                               const float* __restrict__ wg,
                               const float* __restrict__ wfc) {
    const long long i4 = ((long long)blockIdx.x * 256 + threadIdx.x) * 4;
    const float* src; __half* dst; long long off;
    if      (i4 < N_ENC)                        { src = enc; dst = g_ench; off = i4; }
    else if (i4 < N_ENC + N_WQ)                 { src = wq;  dst = g_Wqh;  off = i4 - N_ENC; }
    else if (i4 < N_ENC + 2*N_WQ)               { src = wk;  dst = g_Wkh;  off = i4 - N_ENC - N_WQ; }
    else if (i4 < N_ENC + 2*N_WQ + N_WV)        { src = wv;  dst = g_Wvh;  off = i4 - N_ENC - 2*N_WQ; }
    else if (i4 < N_ENC + 2*N_WQ + 2*N_WV)      { src = wg;  dst = g_Wgh;  off = i4 - N_ENC - 2*N_WQ - N_WV; }
    else if (i4 < N_ENC + 3*N_WQ + 2*N_WV)      { src = wfc; dst = g_Wfch; off = i4 - N_ENC - 2*N_WQ - 2*N_WV; }
    else return;
    const float4 v = *reinterpret_cast<const float4*>(src + off);
    __half2* d2 = reinterpret_cast<__half2*>(dst + off);
    d2[0] = __floats2half2_rn(v.x, v.y);
    d2[1] = __floats2half2_rn(v.z, v.w);
}

// ---------------- mask prep --------------------------------------------------
__global__ void prep_mask(const unsigned char* __restrict__ mask8) {
    __shared__ int s_violate;
    __shared__ int s_len[BATCH];
    const int t = threadIdx.x;
    if (t == 0) s_violate = 0;
    if (t < BATCH) s_len[t] = LSEQ;
    __syncthreads();
    for (int i = t; i < BATCH*LSEQ - 1; i += blockDim.x) {
        if ((i & (LSEQ-1)) != LSEQ-1) {
            if (mask8[i] != 0 && mask8[i+1] == 0) atomicOr(&s_violate, 1);
        }
    }
    __syncthreads();
    const bool is4 = (s_violate != 0);
    if (!is4) {
        for (int i = t; i < BATCH*LSEQ; i += blockDim.x)
            if (mask8[i] != 0) atomicMin(&s_len[i >> 10], i & (LSEQ-1));
    } else {
        const unsigned int* m32 = reinterpret_cast<const unsigned int*>(mask8);
        for (int i = t; i < BATCH*LSEQ; i += blockDim.x)
            if (m32[i] != 0) atomicMin(&s_len[i >> 10], i & (LSEQ-1));
    }
    __syncthreads();
    if (t < BATCH) g_len[t] = s_len[t];
}

// ---------------- fp16 mma GEMM: C = A @ B^T ---------------------------------
// BM=BN=128, BK=64 halfs, 256 threads (8 warps, 64x32 warp tiles), 3-stage
// cp.async pipeline, canonical ldmatrix.x4 b16 fragment loads both operands.
// MODE: 2 fp32 plain batched (S); 7 fp16 plain batched (PV->O);
//       3 fp16 +bias[batch*sBias+n] (gate); 4 fp32 final (+bias+resid,pad0);
//       5 fused QKV (bx<4 Q, <8 K -> fp16 [h][m][dk]; else V -> transposed
//         fp16 Vt[h][b][dv][l] via smem staging)
// SKIP: 1 row-tile skip; 2 S row+col skip; 3 PV row skip + K clamp;
//       4 final zero-fill padded rows.
#define ASTRH   72                  // halfs per smem row (64 data + 8 pad)
#define ABYTES  (128*ASTRH*2)       // 18432
#define STAGEB  (2*ABYTES)          // 36864
#define SMEM_SZ (3*STAGEB)          // 110592
#define SREG    136                 // transpose staging stride (halfs)

template<int MODE, int SKIP>
__global__ void __launch_bounds__(256, 2)
gemm_mma(const __half* __restrict__ A, long long sA,
         const __half* __restrict__ Bm, long long sB,
         int M, int N, int K,
         void* __restrict__ C, long long sC,
         const float* __restrict__ bias, int sBias,
         const float* __restrict__ resid,
         const __half* B2, const float* bias2, void* C2,
         const __half* B3, const float* bias3, void* C3)
{
    extern __shared__ char dsm[];
    const int tid  = threadIdx.x;
    const int w    = tid >> 5;
    const int lane = tid & 31;
    const int wm   = w & 1;
    const int wn   = w >> 1;
    const int batch = blockIdx.z;
    const int bm = blockIdx.y * 128;

    const __half* Bsrc = Bm;
    const float* biasp = bias;
    void* Cp = C;
    int bn = blockIdx.x * 128;
    int smode = MODE;                 // 0 = QK store, 6 = V transposed store
    if (MODE == 5) {
        const int bx = blockIdx.x;
        if (bx < 4)      { smode = 0; bn = bx * 128; }
        else if (bx < 8) { smode = 0; bn = (bx-4) * 128; Bsrc = B2; biasp = bias2; Cp = C2; }
        else             { smode = 6; bn = (bx-8) * 128; Bsrc = B3; biasp = bias3; Cp = C3; }
    }

    int Keff = K;
    if (SKIP == 1) {
        if ((bm & (LSEQ-1)) >= g_len[bm >> 10]) return;
    } else if (SKIP == 2) {
        const int L = g_len[batch & (BATCH-1)];
        if (bm >= L || bn >= L) return;
    } else if (SKIP == 3) {
        const int L = g_len[batch & (BATCH-1)];
        if (bm >= L) return;
        Keff = (L + 63) & ~63;
    } else if (SKIP == 4) {
        if ((bm & (LSEQ-1)) >= g_len[bm >> 10]) {
            float* Cf = (float*)Cp;
            const float4 z = {0.f, 0.f, 0.f, 0.f};
            for (int i = tid; i < 128*32; i += 256) {
                const int r = i >> 5, c4 = i & 31;
                *reinterpret_cast<float4*>(&Cf[(long long)(bm + r)*N + bn + c4*4]) = z;
            }
            return;
        }
    }

    const __half* Ab = A    + (long long)batch * sA;
    const __half* Bb = Bsrc + (long long)batch * sB;
    const uint32_t smem0 = smem_u32(dsm);
    const int KC = Keff >> 6;                         // BK = 64 halfs

    auto load_stage = [&](int kc) {
        const int st = kc % 3;
        const uint32_t sa = smem0 + st * STAGEB;
        const uint32_t sb = sa + ABYTES;
        const int k0 = kc << 6;
        #pragma unroll
        for (int i = 0; i < 4; i++) {                 // A: 128 rows x 8 chunks
            const int idx = tid + i * 256;
            const int row = idx >> 3, chk = idx & 7;
            cp16(sa + row*(ASTRH*2) + chk*16,
                 Ab + (long long)(bm + row) * K + k0 + chk*8);
        }
        #pragma unroll
        for (int i = 0; i < 4; i++) {                 // B
            const int idx = tid + i * 256;
            const int row = idx >> 3, chk = idx & 7;
            cp16(sb + row*(ASTRH*2) + chk*16,
                 Bb + (long long)(bn + row) * K + k0 + chk*8);
        }
        asm volatile("cp.async.commit_group;" ::: "memory");
    };

    float acc[4][4][4];
    #pragma unroll
    for (int i = 0; i < 4; i++)
        #pragma unroll
        for (int j = 0; j < 4; j++)
            #pragma unroll
            for (int q = 0; q < 4; q++) acc[i][j][q] = 0.f;

    load_stage(0);
    if (KC > 1) load_stage(1);

    // ldmatrix lane-derived offsets (canonical b16 x4 patterns)
    const int lrow_a  = lane & 15;                       // m-row in 16x16 tile
    const int lkoff_a = (lane >> 4) * 8;                 // k half: 0 or 8
    const int lrow_b  = (lane & 7) + ((lane >> 4) << 3); // n-row 0..15
    const int lkoff_b = (lane & 8) ? 8 : 0;              // k half: 0 or 8

    for (int kc = 0; kc < KC; kc++) {
        if (kc + 1 < KC) asm volatile("cp.async.wait_group 1;" ::: "memory");
        else             asm volatile("cp.async.wait_group 0;" ::: "memory");
        __syncthreads();
        if (kc + 2 < KC) load_stage(kc + 2);

        const int st = kc % 3;
        const uint32_t Abase = smem0 + st * STAGEB;
        const uint32_t Bbase = Abase + ABYTES;

        #pragma unroll
        for (int ks = 0; ks < 4; ks++) {                 // 4 k-steps of 16
            uint32_t af[4][4];
            #pragma unroll
            for (int mt = 0; mt < 4; mt++) {
                const uint32_t addr = Abase +
                    ((wm*64 + mt*16 + lrow_a)*ASTRH + ks*16 + lkoff_a) * 2;
                ldsm4(af[mt][0], af[mt][1], af[mt][2], af[mt][3], addr);
            }
            uint32_t bf[4][2];
            #pragma unroll
            for (int np = 0; np < 2; np++) {
                const uint32_t addr = Bbase +
                    ((wn*32 + np*16 + lrow_b)*ASTRH + ks*16 + lkoff_b) * 2;
                ldsm4(bf[np*2][0], bf[np*2][1], bf[np*2+1][0], bf[np*2+1][1], addr);
            }
            #pragma unroll
            for (int mt = 0; mt < 4; mt++)
                #pragma unroll
                for (int nt = 0; nt < 4; nt++)
                    mma_f16(acc[mt][nt][0], acc[mt][nt][1], acc[mt][nt][2], acc[mt][nt][3],
                            af[mt][0], af[mt][1], af[mt][2], af[mt][3],
                            bf[nt][0], bf[nt][1]);
        }
    }

    // ---------------- V transposed store via smem staging (smode 6) ----------
    if (MODE == 5 && smode == 6) {
        __syncthreads();                              // pipeline smem now free
        __half* stg = reinterpret_cast<__half*>(dsm); // [128 dv][SREG l]
        #pragma unroll
        for (int mt = 0; mt < 4; mt++) {
            #pragma unroll
            for (int half_ = 0; half_ < 2; half_++) {
                const int ml = wm*64 + mt*16 + (lane >> 2) + half_*8;   // l-local
                #pragma unroll
                for (int nt = 0; nt < 4; nt++) {
                    const int nl = wn*32 + nt*8 + (lane & 3)*2;         // dv-local
                    const float2 bv = *reinterpret_cast<const float2*>(&biasp[bn + nl]);
                    stg[nl*SREG + ml]     = __float2half_rn(acc[mt][nt][half_*2 + 0] + bv.x);
                    stg[(nl+1)*SREG + ml] = __float2half_rn(acc[mt][nt][half_*2 + 1] + bv.y);
                }
            }
        }
        __syncthreads();
        const int h = bn >> 9, dv0 = bn & 511;
        const int b = bm >> 10, l0 = bm & (LSEQ-1);
        __half* Vt = (__half*)Cp + (((long long)h*BATCH + b)*DVH + dv0)*LSEQ + l0;
        #pragma unroll
        for (int i = 0; i < 8; i++) {                 // 128 dv x 16 l-chunks
            const int u = tid + i*256;
            const int dv = u >> 4, lc = u & 15;
            const uint4 o = *reinterpret_cast<const uint4*>(&stg[dv*SREG + lc*8]);
            *reinterpret_cast<uint4*>(&Vt[(long long)dv*LSEQ + lc*8]) = o;
        }
        return;
    }

    // ---------------- generic epilogue ----------------------------------------
    #pragma unroll
    for (int mt = 0; mt < 4; mt++) {
        const int r0 = bm + wm*64 + mt*16 + (lane >> 2);
        #pragma unroll
        for (int half_ = 0; half_ < 2; half_++) {
            const int m = r0 + half_*8;
            const int b_idx = m >> 10, l_idx = m & (LSEQ-1);
            #pragma unroll
            for (int nt = 0; nt < 4; nt++) {
                const int n = bn + wn*32 + nt*8 + (lane & 3)*2;
                const float v0 = acc[mt][nt][half_*2 + 0];
                const float v1 = acc[mt][nt][half_*2 + 1];
                if (MODE == 5) {      // QK projection: fp16 [h][m][dk] + bias
                    const float2 bv = *reinterpret_cast<const float2*>(&biasp[n]);
                    const int h = n >> 6, d = n & 63;
                    __half* Ch = (__half*)Cp;
                    *reinterpret_cast<__half2*>(&Ch[((long long)h*MTOT + m)*DKH + d]) =
                        __floats2half2_rn(v0 + bv.x, v1 + bv.y);
                } else if (MODE == 2) {   // fp32 plain batched (S)
                    float2 o = {v0, v1};
                    *reinterpret_cast<float2*>(
                        &((float*)Cp)[(long long)batch*sC + (long long)m*N + n]) = o;
                } else if (MODE == 7) {   // fp16 plain batched (O)
                    __half* Ch = (__half*)Cp;
                    *reinterpret_cast<__half2*>(
                        &Ch[(long long)batch*sC + (long long)m*N + n]) =
                        __floats2half2_rn(v0, v1);
                } else if (MODE == 3) {   // fp16 + per-batch bias (G)
                    const float2 bv = *reinterpret_cast<const float2*>(
                        &biasp[(long long)batch*sBias + n]);
                    __half* Ch = (__half*)Cp;
                    *reinterpret_cast<__half2*>(
                        &Ch[(long long)batch*sC + (long long)m*N + n]) =
                        __floats2half2_rn(v0 + bv.x, v1 + bv.y);
                } else {                  // MODE 4: fp32 final
                    float* Cf = (float*)Cp;
                    float2 o;
                    if (l_idx >= g_len[b_idx]) { o.x = 0.f; o.y = 0.f; }
                    else {
                        const float2 bv = *reinterpret_cast<const float2*>(&biasp[n]);
                        const float2 rv = *reinterpret_cast<const float2*>(
                            &resid[(long long)m*N + n]);
                        o.x = v0 + bv.x + rv.x;
                        o.y = v1 + bv.y + rv.y;
                    }
                    *reinterpret_cast<float2*>(&Cf[(long long)m*N + n]) = o;
                }
            }
        }
    }
}

// ---------------- masked row softmax: fp32 in (S), fp16 out (P) --------------
__global__ void softmax_rows(const float* __restrict__ S, __half* __restrict__ P) {
    const int hb  = blockIdx.y;
    const int len = g_len[hb & (BATCH-1)];
    const int q   = blockIdx.x;
    if (q >= len) return;                  // padded rows: P stays 0 (zero-init)
    const float4* row = reinterpret_cast<const float4*>(
        S + ((long long)hb * LSEQ + q) * LSEQ);
    __half2* prow = reinterpret_cast<__half2*>(
        P + ((long long)hb * LSEQ + q) * LSEQ);

    const int t = threadIdx.x;
    const float4 v = row[t];
    const int j0 = t * 4;
    const float NEG = -1e30f;
    float x0 = (j0+0 < len) ? v.x : NEG;
    float x1 = (j0+1 < len) ? v.y : NEG;
    float x2 = (j0+2 < len) ? v.z : NEG;
    float x3 = (j0+3 < len) ? v.w : NEG;

    __shared__ float rmax[8], rsum[8];
    float mx = fmaxf(fmaxf(x0, x1), fmaxf(x2, x3));
    #pragma unroll
    for (int o = 16; o; o >>= 1) mx = fmaxf(mx, __shfl_xor_sync(~0u, mx, o));
    if ((t & 31) == 0) rmax[t >> 5] = mx;
    __syncthreads();
    mx = rmax[0];
    #pragma unroll
    for (int i = 1; i < 8; i++) mx = fmaxf(mx, rmax[i]);
    mx *= 0.125f;

    const float e0 = __expf(x0*0.125f - mx);
    const float e1 = __expf(x1*0.125f - mx);
    const float e2 = __expf(x2*0.125f - mx);
    const float e3 = __expf(x3*0.125f - mx);
    float s = e0 + e1 + e2 + e3;
    #pragma unroll
    for (int o = 16; o; o >>= 1) s += __shfl_xor_sync(~0u, s, o);
    if ((t & 31) == 0) rsum[t >> 5] = s;
    __syncthreads();
    s = rsum[0];
    #pragma unroll
    for (int i = 1; i < 8; i++) s += rsum[i];
    const float inv = 1.f / s;

    prow[t*2]   = __floats2half2_rn(e0*inv, e1*inv);   // exact 0 beyond len
    prow[t*2+1] = __floats2half2_rn(e2*inv, e3*inv);
}

// ---------------- head-gate softmax + weighted combine (fp16 in/out) ---------
__global__ void gate_combine(const __half* __restrict__ G,
                             const __half* __restrict__ O,
                             __half* __restrict__ Y) {
    const int HS4 = MTOT*DVH/4;
    const int i = blockIdx.x * blockDim.x + threadIdx.x;
    if (i >= HS4) return;
    const int m = i >> 7;
    if ((m & (LSEQ-1)) >= g_len[m >> 10]) return;     // padded: Y stays 0

    const uint2* G4 = reinterpret_cast<const uint2*>(G);
    const uint2* O4 = reinterpret_cast<const uint2*>(O);
    float g[NHEAD][4];
    float mx0 = -1e30f, mx1 = -1e30f, mx2 = -1e30f, mx3 = -1e30f;
    #pragma unroll
    for (int h = 0; h < NHEAD; h++) {
        const uint2 u = G4[(long long)h*HS4 + i];
        const float2 a = __half22float2(*reinterpret_cast<const __half2*>(&u.x));
        const float2 b = __half22float2(*reinterpret_cast<const __half2*>(&u.y));
        g[h][0] = a.x; g[h][1] = a.y; g[h][2] = b.x; g[h][3] = b.y;
        mx0 = fmaxf(mx0, a.x); mx1 = fmaxf(mx1, a.y);
        mx2 = fmaxf(mx2, b.x); mx3 = fmaxf(mx3, b.y);
    }
    float acc0=0, acc1=0, acc2=0, acc3=0, s0=0, s1=0, s2=0, s3=0;
    #pragma unroll
    for (int h = 0; h < NHEAD; h++) {
        const uint2 u = O4[(long long)h*HS4 + i];
        const float2 a = __half22float2(*reinterpret_cast<const __half2*>(&u.x));
        const float2 b = __half22float2(*reinterpret_cast<const __half2*>(&u.y));
        const float e0 = __expf(g[h][0] - mx0), e1 = __expf(g[h][1] - mx1);
        const float e2 = __expf(g[h][2] - mx2), e3 = __expf(g[h][3] - mx3);
        s0 += e0; s1 += e1; s2 += e2; s3 += e3;
        acc0 += e0*a.x; acc1 += e1*a.y; acc2 += e2*b.x; acc3 += e3*b.y;
    }
    uint2 o;
    *reinterpret_cast<__half2*>(&o.x) = __floats2half2_rn(acc0/s0, acc1/s1);
    *reinterpret_cast<__half2*>(&o.y) = __floats2half2_rn(acc2/s2, acc3/s3);
    reinterpret_cast<uint2*>(Y)[i] = o;
}

// ---------------- launch ------------------------------------------------------
extern "C" void kernel_launch(void* const* d_in, const int* in_sizes, int n_in,
                              void* d_out, int out_size) {
    const float*         enc  = (const float*)d_in[0];
    const unsigned char* npm  = (const unsigned char*)d_in[1];
    const float* w_q  = (const float*)d_in[3];
    const float* b_q  = (const float*)d_in[4];
    const float* w_k  = (const float*)d_in[5];
    const float* b_k  = (const float*)d_in[6];
    const float* w_v  = (const float*)d_in[7];
    const float* b_v  = (const float*)d_in[8];
    const float* w_g  = (const float*)d_in[9];
    const float* b_g  = (const float*)d_in[10];
    const float* w_fc = (const float*)d_in[11];
    const float* b_fc = (const float*)d_in[12];
    float* out = (float*)d_out;

    __half *pEnc,*pWq,*pWk,*pWv,*pWg,*pWfc,*pQ,*pK,*pVt,*pP,*pO,*pG,*pY;
    float *pS;
    cudaGetSymbolAddress((void**)&pEnc, g_ench);
    cudaGetSymbolAddress((void**)&pWq,  g_Wqh);
    cudaGetSymbolAddress((void**)&pWk,  g_Wkh);
    cudaGetSymbolAddress((void**)&pWv,  g_Wvh);
    cudaGetSymbolAddress((void**)&pWg,  g_Wgh);
    cudaGetSymbolAddress((void**)&pWfc, g_Wfch);
    cudaGetSymbolAddress((void**)&pQ,   g_Q);
    cudaGetSymbolAddress((void**)&pK,   g_K);
    cudaGetSymbolAddress((void**)&pVt,  g_Vt);
    cudaGetSymbolAddress((void**)&pS,   g_S);
    cudaGetSymbolAddress((void**)&pP,   g_P);
    cudaGetSymbolAddress((void**)&pO,   g_O);
    cudaGetSymbolAddress((void**)&pG,   g_G);
    cudaGetSymbolAddress((void**)&pY,   g_Y);

    cudaFuncSetAttribute(gemm_mma<5,1>, cudaFuncAttributeMaxDynamicSharedMemorySize, SMEM_SZ);
    cudaFuncSetAttribute(gemm_mma<2,2>, cudaFuncAttributeMaxDynamicSharedMemorySize, SMEM_SZ);
    cudaFuncSetAttribute(gemm_mma<7,3>, cudaFuncAttributeMaxDynamicSharedMemorySize, SMEM_SZ);
    cudaFuncSetAttribute(gemm_mma<3,1>, cudaFuncAttributeMaxDynamicSharedMemorySize, SMEM_SZ);
    cudaFuncSetAttribute(gemm_mma<4,4>, cudaFuncAttributeMaxDynamicSharedMemorySize, SMEM_SZ);

    const int M = MTOT;              // 8192
    dim3 blk(256);

    convert_inputs<<<(N_ENC + 3*N_WQ + 2*N_WV) / 1024, 256>>>(enc, w_q, w_k, w_v, w_g, w_fc);
    prep_mask<<<1, 256>>>(npm);

    // Fused Q/K/V projections (fp16): Q,K -> [h][m][dk]; V -> Vt[h][b][dv][l]
    gemm_mma<5,1><<<dim3(40, M/128, 1), blk, SMEM_SZ>>>(
        pEnc,0, pWq,0, M, NHEAD*DKH, DMODEL, pQ,0, b_q,0, nullptr,
        pWk, b_k, pK, pWv, b_v, pVt);
    // S = Q @ K^T per (h,b), fp32 out, masked tiles skipped
    gemm_mma<2,2><<<dim3(LSEQ/128, LSEQ/128, NHEAD*BATCH), blk, SMEM_SZ>>>(
        pQ,(long long)LSEQ*DKH, pK,(long long)LSEQ*DKH,
        LSEQ, LSEQ, DKH, pS,(long long)LSEQ*LSEQ, nullptr,0, nullptr,
        nullptr,nullptr,nullptr, nullptr,nullptr,nullptr);
    softmax_rows<<<dim3(LSEQ, NHEAD*BATCH), 256>>>(pS, pP);
    // O = P @ Vt^T per (h,b), fp16 out, K clamped to len
    gemm_mma<7,3><<<dim3(DVH/128, LSEQ/128, NHEAD*BATCH), blk, SMEM_SZ>>>(
        pP,(long long)LSEQ*LSEQ, pVt,(long long)DVH*LSEQ,
        LSEQ, DVH, LSEQ, pO,(long long)LSEQ*DVH, nullptr,0, nullptr,
        nullptr,nullptr,nullptr, nullptr,nullptr,nullptr);
    // gate logits: batched over heads, per-head bias, fp16 out
    gemm_mma<3,1><<<dim3(DVH/128, M/128, NHEAD), blk, SMEM_SZ>>>(
        pO,(long long)M*DVH, pWg,(long long)DVH*DMODEL,
        M, DVH, DMODEL, pG,(long long)M*DVH, b_g, DVH, nullptr,
        nullptr,nullptr,nullptr, nullptr,nullptr,nullptr);
    gate_combine<<<(M*DVH/4 + 255)/256, 256>>>(pG, pO, pY);
    // final FC + bias + residual + pad zeroing (fp32 out)
    gemm_mma<4,4><<<dim3(DMODEL/128, M/128, 1), blk, SMEM_SZ>>>(
        pY,0, pWfc,0, M, DMODEL, DVH, out,0, b_fc,0, enc,
        nullptr,nullptr,nullptr, nullptr,nullptr,nullptr);
}